// round 12
// baseline (speedup 1.0000x reference)
#include <cuda_runtime.h>
#include <cuda_fp16.h>
#include <cstdint>

#define NGRAPH 8192
#define NNODE (NGRAPH * 32)
#define NEDGE 524288

typedef __half h16;

// ================= static device scratch =================
__device__ __align__(16) h16  g_adjh[NGRAPH * 1024];   // fp16 counts
__device__ __align__(16) h16  g_featH[(size_t)NNODE * 128];
__device__ __align__(16) h16  g_AggH[(size_t)NNODE * 256];
__device__ __align__(16) h16  g_HNh[(size_t)NNODE * 128];
__device__ __align__(16) float g_HNlast[(size_t)NGRAPH * 128];
__device__ __align__(16) float g_FV[(size_t)NGRAPH * 128];
__device__ __align__(16) h16  g_Wio[256 * 128];
__device__ __align__(16) h16  g_Wg[512 * 384];
__device__ __align__(16) h16  g_Wu[128 * 128];
__device__ __align__(16) h16  g_Wv[128 * 128];
__device__ __align__(16) float g_biasY[256];
__device__ __align__(16) float g_biasG[512];

// ================= helpers =================
__device__ __forceinline__ uint32_t smem_to_u32(const void* p) {
  uint32_t a;
  asm("{ .reg .u64 tmp; cvta.to.shared.u64 tmp, %1; cvt.u32.u64 %0, tmp; }"
      : "=r"(a) : "l"(p));
  return a;
}
#define SWZ(off) ((off) ^ (((off) >> 3) & 0x70))

__device__ __forceinline__ void cp16(uint32_t dst, const void* src) {
  asm volatile("cp.async.cg.shared.global [%0], [%1], 16;" ::"r"(dst), "l"(src));
}
#define CP_COMMIT() asm volatile("cp.async.commit_group;" ::: "memory")
#define CP_WAIT(n) asm volatile("cp.async.wait_group %0;" ::"n"(n) : "memory")

__device__ __forceinline__ void ldsm_x4(uint32_t addr, uint32_t* r) {
  asm volatile("ldmatrix.sync.aligned.m8n8.x4.shared.b16 {%0,%1,%2,%3}, [%4];"
               : "=r"(r[0]), "=r"(r[1]), "=r"(r[2]), "=r"(r[3]) : "r"(addr));
}
__device__ __forceinline__ void ldsm_x4_t(uint32_t addr, uint32_t* r) {
  asm volatile("ldmatrix.sync.aligned.m8n8.x4.trans.shared.b16 {%0,%1,%2,%3}, [%4];"
               : "=r"(r[0]), "=r"(r[1]), "=r"(r[2]), "=r"(r[3]) : "r"(addr));
}
__device__ __forceinline__ void mma16816(float* d, const uint32_t* a,
                                         const uint32_t* b) {
  asm volatile(
      "mma.sync.aligned.m16n8k16.row.col.f32.f16.f16.f32 "
      "{%0,%1,%2,%3}, {%4,%5,%6,%7}, {%8,%9}, {%0,%1,%2,%3};"
      : "+f"(d[0]), "+f"(d[1]), "+f"(d[2]), "+f"(d[3])
      : "r"(a[0]), "r"(a[1]), "r"(a[2]), "r"(a[3]), "r"(b[0]), "r"(b[1]));
}

__device__ __forceinline__ float sigf(float x) { return 1.f / (1.f + __expf(-x)); }
__device__ __forceinline__ float tanh_fast(float x) {
  float e2x = __expf(2.f * x);
  return 1.f - 2.f / (e2x + 1.f);
}
__device__ __forceinline__ float h2f(h16 v) { return __half2float(v); }
__device__ __forceinline__ uint32_t pack2h(float a, float b) {
  __half2 h = __floats2half2_rn(a, b);
  return *(uint32_t*)&h;
}

// ================= adjacency (fp16 direct) =================
__global__ void k_zero_adj() {
  int i = blockIdx.x * blockDim.x + threadIdx.x;
  int stride = gridDim.x * blockDim.x;
  int4* p = (int4*)g_adjh;
  const int n4 = NGRAPH * 1024 * 2 / 16;
  int4 z = make_int4(0, 0, 0, 0);
  for (; i < n4; i += stride) p[i] = z;
}
__global__ void k_build_adj(const int* __restrict__ src, const int* __restrict__ dst) {
  int e = blockIdx.x * blockDim.x + threadIdx.x;
  if (e >= NEDGE) return;
  int d = dst[e];
  int s = src[e];
  int idx = ((d >> 5) << 10) + ((d & 31) << 5) + (s & 31);
  __half2 v = (idx & 1) ? __floats2half2_rn(0.f, 1.f)
                        : __floats2half2_rn(1.f, 0.f);
  atomicAdd(&((__half2*)g_adjh)[idx >> 1], v);
}

// ================= weight pack + feat convert =================
__global__ void k_pack(const float* __restrict__ feat,
                       const float* __restrict__ W_in, const float* __restrict__ W_og,
                       const float* __restrict__ W_ih, const float* __restrict__ W_hh,
                       const float* __restrict__ W_u, const float* __restrict__ W_v,
                       const float* __restrict__ b_in, const float* __restrict__ b_og,
                       const float* __restrict__ b_ih, const float* __restrict__ b_hh) {
  int i0 = blockIdx.x * 256 + threadIdx.x;
  int stride = gridDim.x * 256;
  {
    const float4* f4 = (const float4*)feat;
    const size_t n4 = (size_t)NNODE * 32;
    for (size_t i = i0; i < n4; i += stride) {
      float4 v = f4[i];
      __half2* dstp = (__half2*)&g_featH[i * 4];
      dstp[0] = __floats2half2_rn(v.x, v.y);
      dstp[1] = __floats2half2_rn(v.z, v.w);
    }
  }
  for (int i = i0; i < 256 * 128; i += stride) {
    int r = i >> 7, c = i & 127;
    float v = (r < 128) ? W_in[r * 128 + c] : W_og[(r - 128) * 128 + c];
    g_Wio[i] = __float2half_rn(v);
  }
  for (int i = i0; i < 512 * 384; i += stride) {
    int r = i / 384, c = i % 384;
    int blk = r >> 7, rr = r & 127;
    float v;
    if (blk == 0)      v = (c < 256) ? W_ih[rr * 256 + c] : W_hh[rr * 128 + (c - 256)];
    else if (blk == 1) v = (c < 256) ? W_ih[(128 + rr) * 256 + c] : W_hh[(128 + rr) * 128 + (c - 256)];
    else if (blk == 2) v = (c < 256) ? W_ih[(256 + rr) * 256 + c] : 0.f;
    else               v = (c < 256) ? 0.f : W_hh[(256 + rr) * 128 + (c - 256)];
    g_Wg[i] = __float2half_rn(v);
  }
  for (int i = i0; i < 128 * 128; i += stride) {
    g_Wu[i] = __float2half_rn(W_u[i]);
    g_Wv[i] = __float2half_rn(W_v[i]);
  }
  for (int i = i0; i < 256; i += stride)
    g_biasY[i] = (i < 128) ? b_in[i] : b_og[i - 128];
  for (int i = i0; i < 512; i += stride) {
    float v;
    if (i < 256)      v = b_ih[i] + b_hh[i];
    else if (i < 384) v = b_ih[i];
    else              v = b_hh[i - 128];
    g_biasG[i] = v;
  }
}

// ================= Y GEMM + tensorized aggregation (2 CTA/SM) ====
#define YSG 32768
#define Y_ADJ 65536
#define Y_RDEG (65536 + 10240)
#define SM_YAGG (65536 + 10240 + 512)

__global__ void __launch_bounds__(256, 2) k_yagg() {
  extern __shared__ __align__(1024) char smem[];
  const uint32_t sb = smem_to_u32(smem);
  const int tid = threadIdx.x;
  const int lid = tid & 31, wid = tid >> 5;
  const int m0 = blockIdx.x * 128;
  const int nb = blockIdx.y;
  const int g0 = m0 >> 5;
  const int wm0 = (wid & 3) * 32, wn0 = (wid >> 2) * 64;

  const h16* Bh = g_Wio + (size_t)nb * 128 * 128;
  float* rdeg = (float*)(smem + Y_RDEG);

  auto issue = [&](int kc, int s) {
    uint32_t base = sb + s * YSG;
#pragma unroll
    for (int i = 0; i < 4; i++) {
      int u = tid + 256 * i;
      int r = u >> 3, seg = u & 7;
      uint32_t d = SWZ(r * 128 + seg * 16);
      cp16(base + d, g_featH + (size_t)(m0 + r) * 128 + kc + seg * 8);
      cp16(base + 16384 + d, Bh + (size_t)r * 128 + kc + seg * 8);
    }
    CP_COMMIT();
  };

  issue(0, 0);
  issue(64, 1);

  const h16* adjg = g_adjh + ((size_t)g0 << 10);
#pragma unroll
  for (int i = 0; i < 16; i++) {
    int u = tid + 256 * i;
    int gl = u >> 10, rem = u & 1023;
    int n = rem >> 5, k = rem & 31;
    int row, col;
    if (nb == 0) { row = gl * 32 + n; col = k; }
    else { row = gl * 32 + k; col = n; }
    *(h16*)(smem + Y_ADJ + row * 80 + col * 2) = adjg[u];
  }
  __syncthreads();
  if (tid < 128) {
    float s = 0.f;
#pragma unroll
    for (int k = 0; k < 32; k++)
      s += h2f(*(h16*)(smem + Y_ADJ + tid * 80 + k * 2));
    rdeg[tid] = 1.f / fmaxf(s, 1.f);
  }

  float acc[2][8][4];
#pragma unroll
  for (int mi = 0; mi < 2; mi++)
#pragma unroll
    for (int ni = 0; ni < 8; ni++)
#pragma unroll
      for (int q = 0; q < 4; q++) acc[mi][ni][q] = 0.f;

  const int j = lid >> 3, rr = lid & 7;
#pragma unroll
  for (int c = 0; c < 2; c++) {
    if (c == 0) CP_WAIT(1); else CP_WAIT(0);
    __syncthreads();
    const uint32_t st = sb + c * YSG;
#pragma unroll
    for (int kk = 0; kk < 4; kk++) {
      uint32_t ah[2][4], bh[8][2];
#pragma unroll
      for (int mi = 0; mi < 2; mi++) {
        int row = wm0 + mi * 16 + (j & 1) * 8 + rr;
        int kb = kk * 32 + (j >> 1) * 16;
        ldsm_x4(st + SWZ(row * 128 + kb), ah[mi]);
      }
#pragma unroll
      for (int p = 0; p < 4; p++) {
        int n = wn0 + p * 16 + (j >> 1) * 8 + rr;
        int kb = kk * 32 + (j & 1) * 16;
        uint32_t t[4];
        ldsm_x4(st + 16384 + SWZ(n * 128 + kb), t);
        bh[2 * p][0] = t[0]; bh[2 * p][1] = t[1];
        bh[2 * p + 1][0] = t[2]; bh[2 * p + 1][1] = t[3];
      }
#pragma unroll
      for (int mi = 0; mi < 2; mi++)
#pragma unroll
        for (int ni = 0; ni < 8; ni++)
          mma16816(acc[mi][ni], ah[mi], bh[ni]);
    }
  }
  __syncthreads();

  const int gp = lid >> 2, tg = lid & 3;
#pragma unroll
  for (int mi = 0; mi < 2; mi++)
#pragma unroll
    for (int ni = 0; ni < 8; ni++) {
      int r = wm0 + mi * 16 + gp;
      int c = wn0 + ni * 8 + tg * 2;
      float b0 = g_biasY[nb * 128 + c], b1 = g_biasY[nb * 128 + c + 1];
      uint32_t tileo = (c >> 6) * 16384;
      *(uint32_t*)(smem + tileo + SWZ(r * 128 + (c & 63) * 2)) =
          pack2h(acc[mi][ni][0] + b0, acc[mi][ni][1] + b1);
      *(uint32_t*)(smem + tileo + SWZ((r + 8) * 128 + (c & 63) * 2)) =
          pack2h(acc[mi][ni][2] + b0, acc[mi][ni][3] + b1);
    }
  __syncthreads();

  {
    const int arow = wid * 16;
    const int krow0 = (wid >> 1) * 32;
    uint32_t af[2][4];
#pragma unroll
    for (int ks = 0; ks < 2; ks++) {
      uint32_t addr = sb + Y_ADJ + (arow + (j & 1) * 8 + rr) * 80 +
                      (j >> 1) * 16 + ks * 32;
      ldsm_x4(addr, af[ks]);
    }
    float accC[16][4];
#pragma unroll
    for (int nf = 0; nf < 16; nf++)
#pragma unroll
      for (int q = 0; q < 4; q++) accC[nf][q] = 0.f;
#pragma unroll
    for (int p = 0; p < 8; p++) {
#pragma unroll
      for (int ks = 0; ks < 2; ks++) {
        int krow = krow0 + ks * 16 + (j & 1) * 8 + rr;
        int c = p * 16 + (j >> 1) * 8;
        uint32_t t[4];
        ldsm_x4_t(sb + (c >> 6) * 16384 + SWZ(krow * 128 + (c & 63) * 2), t);
        mma16816(accC[2 * p], af[ks], t);
        mma16816(accC[2 * p + 1], af[ks], t + 2);
      }
    }
#pragma unroll
    for (int nf = 0; nf < 16; nf++) {
      int col = nf * 8 + tg * 2;
      int r0 = arow + gp, r1 = arow + gp + 8;
      float rd0 = rdeg[r0], rd1 = rdeg[r1];
      size_t o0 = (size_t)(m0 + r0) * 256 + nb * 128 + col;
      size_t o1 = (size_t)(m0 + r1) * 256 + nb * 128 + col;
      *(uint32_t*)&g_AggH[o0] = pack2h(accC[nf][0] * rd0, accC[nf][1] * rd0);
      *(uint32_t*)&g_AggH[o1] = pack2h(accC[nf][2] * rd1, accC[nf][3] * rd1);
    }
  }
}

// ========== gates: resident-B (72KB), 8 row-blocks/CTA, fused GRU ==========
// grid (512, 4): nh = 32 gate-cols of each gate; blocks m0 = (bx*8+b)*64.
#define GB0   0              // 18 tiles x 4KB = 72KB resident Wg
#define GABUF 73728          // 2 x 48KB A buffers
#define SM_GATES (73728 + 2 * 49152)   // 172032

__global__ void __launch_bounds__(256, 1) k_gates() {
  extern __shared__ __align__(1024) char smem[];
  const uint32_t sb = smem_to_u32(smem);
  const int tid = threadIdx.x;
  const int lid = tid & 31, wid = tid >> 5;
  const int nh = blockIdx.y;
  const int cs = nh * 32;
  const int gate = wid >> 1;
  const int wm0g = (wid & 1) * 32;
  const int j = lid >> 3, rr = lid & 7;
  const int gp = lid >> 2, tg = lid & 3;

  // ---- load resident B: tiles 0-5 r, 6-11 z, 12-15 i, 16-17 h(ch4,5) ----
#pragma unroll
  for (int i = 0; i < 18; i++) {
    int u = tid + 256 * i;       // 0..4607
    int t = u >> 8;
    int line = u & 255;
    int r = line >> 3, seg = line & 7;
    int bg, ch;
    if (t < 12) { bg = t / 6; ch = t % 6; }
    else if (t < 16) { bg = 2; ch = t - 12; }
    else { bg = 3; ch = t - 12; }      // 16->ch4, 17->ch5
    cp16(sb + GB0 + t * 4096 + SWZ(r * 128 + seg * 16),
         g_Wg + (size_t)(bg * 128 + cs + r) * 384 + ch * 64 + seg * 8);
  }

  auto issueA = [&](int blk, int buf) {
    int m0 = blk * 64;
    uint32_t base = sb + GABUF + buf * 49152;
#pragma unroll
    for (int i = 0; i < 12; i++) {
      int u = tid + 256 * i;
      int ch = u >> 9;
      int rem = u & 511;
      int r = rem >> 3, seg = rem & 7;
      const h16* src = (ch < 4)
          ? g_AggH + (size_t)(m0 + r) * 256 + ch * 64 + seg * 8
          : g_featH + (size_t)(m0 + r) * 128 + (ch - 4) * 64 + seg * 8;
      cp16(base + ch * 8192 + SWZ(r * 128 + seg * 16), src);
    }
  };

  issueA(blockIdx.x * 8, 0);
  CP_COMMIT();          // group0 = B + A(0)

  for (int b = 0; b < 8; b++) {
    const int blk = blockIdx.x * 8 + b;
    const int m0 = blk * 64;
    if (b + 1 < 8) { issueA(blk + 1, (b + 1) & 1); CP_COMMIT(); }
    if (b + 1 < 8) CP_WAIT(1); else CP_WAIT(0);
    __syncthreads();

    const uint32_t abuf = sb + GABUF + (b & 1) * 49152;
    float acc[2][4][4];
#pragma unroll
    for (int mi = 0; mi < 2; mi++)
#pragma unroll
      for (int ni = 0; ni < 4; ni++)
#pragma unroll
        for (int q = 0; q < 4; q++) acc[mi][ni][q] = 0.f;

    // ---- mainloop: no syncs (A resident, B permanent) ----
    const int chlo = (gate == 3) ? 4 : 0;
    const int chhi = (gate == 2) ? 4 : 6;
    for (int ch = chlo; ch < chhi; ch++) {
      int t = (gate == 0) ? ch : (gate == 1) ? 6 + ch
              : (gate == 2) ? 12 + ch : 12 + ch;   // gate3: 12+4=16, 12+5=17
      const uint32_t bbase = sb + GB0 + t * 4096;
      const uint32_t abase = abuf + ch * 8192;
#pragma unroll
      for (int kk = 0; kk < 4; kk++) {
        uint32_t ah[2][4], bh[4][2];
#pragma unroll
        for (int mi = 0; mi < 2; mi++) {
          int row = wm0g + mi * 16 + (j & 1) * 8 + rr;
          int kb = kk * 32 + (j >> 1) * 16;
          ldsm_x4(abase + SWZ(row * 128 + kb), ah[mi]);
        }
#pragma unroll
        for (int p = 0; p < 2; p++) {
          int n = p * 16 + (j >> 1) * 8 + rr;
          int kb = kk * 32 + (j & 1) * 16;
          uint32_t t4[4];
          ldsm_x4(bbase + SWZ(n * 128 + kb), t4);
          bh[2 * p][0] = t4[0]; bh[2 * p][1] = t4[1];
          bh[2 * p + 1][0] = t4[2]; bh[2 * p + 1][1] = t4[3];
        }
#pragma unroll
        for (int mi = 0; mi < 2; mi++)
#pragma unroll
          for (int ni = 0; ni < 4; ni++)
            mma16816(acc[mi][ni], ah[mi], bh[ni]);
      }
    }
    __syncthreads();

    // ---- fragment exchange: sG aliases Agg region of CURRENT buffer ----
    float* sG = (float*)(smem + GABUF + (b & 1) * 49152);  // 4*64*32 f32 = 32KB
#pragma unroll
    for (int mi = 0; mi < 2; mi++)
#pragma unroll
      for (int ni = 0; ni < 4; ni++) {
        int r = wm0g + mi * 16 + gp;
        int c = ni * 8 + tg * 2;
        sG[(gate * 64 + r) * 32 + c] = acc[mi][ni][0];
        sG[(gate * 64 + r) * 32 + c + 1] = acc[mi][ni][1];
        sG[(gate * 64 + r + 8) * 32 + c] = acc[mi][ni][2];
        sG[(gate * 64 + r + 8) * 32 + c + 1] = acc[mi][ni][3];
      }
    __syncthreads();

    // ---- GRU elementwise (feat from chunks 4,5 of current buffer) ----
    {
      const int row = tid >> 2, q = tid & 3;
      const int grow = m0 + row;
      const bool lastrow = (grow & 31) == 31;
      __align__(16) h16 oh[8];
#pragma unroll
      for (int c2 = 0; c2 < 4; c2++) {
        int c = q * 8 + c2 * 2;              // local col 0..31
        int colg = cs + c;                   // 0..127
        uint32_t fh = *(uint32_t*)(smem + GABUF + (b & 1) * 49152 + 32768 +
                                   (colg >> 6) * 8192 +
                                   SWZ(row * 128 + (colg & 63) * 2));
        float2 fvp = __half22float2(*(__half2*)&fh);
#pragma unroll
        for (int c1 = 0; c1 < 2; c1++) {
          int cc = c + c1;
          int cg = colg + c1;
          float r_ = sigf(sG[row * 32 + cc] + __ldg(&g_biasG[cg]));
          float z_ = sigf(sG[(64 + row) * 32 + cc] + __ldg(&g_biasG[128 + cg]));
          float is = sG[(128 + row) * 32 + cc] + __ldg(&g_biasG[256 + cg]);
          float hs = sG[(192 + row) * 32 + cc] + __ldg(&g_biasG[384 + cg]);
          float ng = tanh_fast(is + r_ * hs);
          float f = (c1 == 0) ? fvp.x : fvp.y;
          float hn = (1.f - z_) * ng + z_ * f;
          oh[c2 * 2 + c1] = __float2half_rn(hn);
          if (lastrow) g_HNlast[(size_t)(grow >> 5) * 128 + cg] = hn;
        }
      }
      *(int4*)&g_HNh[(size_t)grow * 128 + cs + q * 8] = *(int4*)oh;
    }
    __syncthreads();
  }
}

// ================= FV GEMM (small, 128 thr) =================
#define SG 32768
__global__ void __launch_bounds__(128, 2) k_fv(const float* __restrict__ b_v) {
  extern __shared__ __align__(1024) char smem[];
  const uint32_t sb = smem_to_u32(smem);
  const int tid = threadIdx.x;
  const int lid = tid & 31, wid = tid >> 5;
  const int m0 = blockIdx.x * 128;
  const int wm0 = (wid & 1) * 64, wn0 = (wid >> 1) * 64;

  auto issue = [&](int kc, int s) {
    uint32_t base = sb + s * SG;
#pragma unroll
    for (int i = 0; i < 8; i++) {
      int u = tid + 128 * i;
      int r = u >> 3, seg = u & 7;
      uint32_t d = SWZ(r * 128 + seg * 16);
      cp16(base + d, g_HNh + ((size_t)(m0 + r) * 32 + 31) * 128 + kc + seg * 8);
      cp16(base + 16384 + d, g_Wv + (size_t)r * 128 + kc + seg * 8);
    }
    CP_COMMIT();
  };

  float acc[4][8][4];
#pragma unroll
  for (int mi = 0; mi < 4; mi++)
#pragma unroll
    for (int ni = 0; ni < 8; ni++)
#pragma unroll
      for (int q = 0; q < 4; q++) acc[mi][ni][q] = 0.f;

  issue(0, 0);
  issue(64, 1);
  const int j = lid >> 3, rr = lid & 7;
#pragma unroll
  for (int c = 0; c < 2; c++) {
    if (c == 0) CP_WAIT(1); else CP_WAIT(0);
    __syncthreads();
    const uint32_t st = sb + c * SG;
#pragma unroll
    for (int kk = 0; kk < 4; kk++) {
      uint32_t ah[4][4], bh[8][2];
#pragma unroll
      for (int mi = 0; mi < 4; mi++) {
        int row = wm0 + mi * 16 + (j & 1) * 8 + rr;
        int kb = kk * 32 + (j >> 1) * 16;
        ldsm_x4(st + SWZ(row * 128 + kb), ah[mi]);
      }
#pragma unroll
      for (int p = 0; p < 4; p++) {
        int n = wn0 + p * 16 + (j >> 1) * 8 + rr;
        int kb = kk * 32 + (j & 1) * 16;
        uint32_t t[4];
        ldsm_x4(st + 16384 + SWZ(n * 128 + kb), t);
        bh[2 * p][0] = t[0]; bh[2 * p][1] = t[1];
        bh[2 * p + 1][0] = t[2]; bh[2 * p + 1][1] = t[3];
      }
#pragma unroll
      for (int mi = 0; mi < 4; mi++)
#pragma unroll
        for (int ni = 0; ni < 8; ni++)
          mma16816(acc[mi][ni], ah[mi], bh[ni]);
    }
    __syncthreads();
  }
  const int gp = lid >> 2, tg = lid & 3;
#pragma unroll
  for (int mi = 0; mi < 4; mi++)
#pragma unroll
    for (int ni = 0; ni < 8; ni++) {
      int r0 = m0 + wm0 + mi * 16 + gp;
      int c = wn0 + ni * 8 + tg * 2;
      float b0 = b_v[c], b1 = b_v[c + 1];
      *(float2*)&g_FV[(size_t)r0 * 128 + c] =
          make_float2(acc[mi][ni][0] + b0, acc[mi][ni][1] + b1);
      *(float2*)&g_FV[(size_t)(r0 + 8) * 128 + c] =
          make_float2(acc[mi][ni][2] + b0, acc[mi][ni][3] + b1);
    }
}

// ================= U GEMM + attention + readout (2 CTA/SM) ======
__global__ void __launch_bounds__(256, 2) k_alpha(const float* __restrict__ cnt,
                                                  const float* __restrict__ we,
                                                  float* __restrict__ out) {
  extern __shared__ __align__(1024) char smem[];
  const uint32_t sb = smem_to_u32(smem);
  const int tid = threadIdx.x;
  const int lid = tid & 31, wid = tid >> 5;
  const int m0 = blockIdx.x * 128;
  const int g0 = m0 >> 5;
  const int wm0 = (wid & 3) * 32, wn0 = (wid >> 2) * 64;

  float* sFV = (float*)(smem + 2 * SG);
  float* swe = sFV + 512;
  float* scnt = swe + 128;
  float* sPart = scnt + 128;
  float* sAl = sPart + 256;

  auto issue = [&](int kc, int s) {
    uint32_t base = sb + s * SG;
#pragma unroll
    for (int i = 0; i < 4; i++) {
      int u = tid + 256 * i;
      int r = u >> 3, seg = u & 7;
      uint32_t d = SWZ(r * 128 + seg * 16);
      cp16(base + d, g_HNh + (size_t)(m0 + r) * 128 + kc + seg * 8);
      cp16(base + 16384 + d, g_Wu + (size_t)r * 128 + kc + seg * 8);
    }
    CP_COMMIT();
  };

  issue(0, 0);
  issue(64, 1);
#pragma unroll
  for (int i = 0; i < 2; i++) {
    int e = tid + 256 * i;
    sFV[e] = g_FV[(size_t)(g0 + (e >> 7)) * 128 + (e & 127)];
  }
  if (tid < 128) { swe[tid] = we[tid]; scnt[tid] = cnt[m0 + tid]; }

  float acc[2][8][4];
#pragma unroll
  for (int mi = 0; mi < 2; mi++)
#pragma unroll
    for (int ni = 0; ni < 8; ni++)
#pragma unroll
      for (int q = 0; q < 4; q++) acc[mi][ni][q] = 0.f;

  const int j = lid >> 3, rr = lid & 7;
#pragma unroll
  for (int c = 0; c < 2; c++) {
    if (c == 0) CP_WAIT(1); else CP_WAIT(0);
    __syncthreads();
    const uint32_t st = sb + c * SG;
#pragma unroll
    for (int kk = 0; kk < 4; kk++) {
      uint32_t ah[2][4], bh[8][2];
#pragma unroll
      for (int mi = 0; mi < 2; mi++) {
        int row = wm0 + mi * 16 + (j & 1) * 8 + rr;
        int kb = kk * 32 + (j >> 1) * 16;
        ldsm_x4(st + SWZ(row * 128 + kb), ah[mi]);
      }
#pragma unroll
      for (int p = 0; p < 4; p++) {
        int n = wn0 + p * 16 + (j >> 1) * 8 + rr;
        int kb = kk * 32 + (j & 1) * 16;
        uint32_t t[4];
        ldsm_x4(st + 16384 + SWZ(n * 128 + kb), t);
        bh[2 * p][0] = t[0]; bh[2 * p][1] = t[1];
        bh[2 * p + 1][0] = t[2]; bh[2 * p + 1][1] = t[3];
      }
#pragma unroll
      for (int mi = 0; mi < 2; mi++)
#pragma unroll
        for (int ni = 0; ni < 8; ni++)
          mma16816(acc[mi][ni], ah[mi], bh[ni]);
    }
  }
  __syncthreads();

  const int gp = lid >> 2, tg = lid & 3;
#pragma unroll
  for (int mi = 0; mi < 2; mi++) {
    int base = wm0 + mi * 16;
    int gl = base >> 5;
    float p0 = 0.f, p1 = 0.f;
#pragma unroll
    for (int ni = 0; ni < 8; ni++) {
      int jx = wn0 + ni * 8 + tg * 2;
      float fv0 = sFV[gl * 128 + jx], fv1 = sFV[gl * 128 + jx + 1];
      float w0 = swe[jx], w1 = swe[jx + 1];
      p0 += w0 * sigf(acc[mi][ni][0] + fv0) + w1 * sigf(acc[mi][ni][1] + fv1);
      p1 += w0 * sigf(acc[mi][ni][2] + fv0) + w1 * sigf(acc[mi][ni][3] + fv1);
    }
    p0 += __shfl_xor_sync(0xffffffffu, p0, 1);
    p0 += __shfl_xor_sync(0xffffffffu, p0, 2);
    p1 += __shfl_xor_sync(0xffffffffu, p1, 1);
    p1 += __shfl_xor_sync(0xffffffffu, p1, 2);
    if (tg == 0) {
      sPart[(wid >> 2) * 128 + base + gp] = p0;
      sPart[(wid >> 2) * 128 + base + gp + 8] = p1;
    }
  }
  __syncthreads();
  if (tid < 128) sAl[tid] = (sPart[tid] + sPart[128 + tid]) * scnt[tid];
  __syncthreads();

#pragma unroll
  for (int v = 0; v < 2; v++) {
    int idx = tid + v * 256;
    int gl = idx >> 7, jx = idx & 127;
    int stg = jx >> 6, cidx = jx & 63;
    float accg = 0.f;
#pragma unroll
    for (int n = 0; n < 32; n++) {
      float hn = h2f(*(h16*)(smem + stg * SG + SWZ((gl * 32 + n) * 128 + cidx * 2)));
      accg += hn * sAl[gl * 32 + n];
    }
    out[(size_t)(g0 + gl) * 256 + jx] = accg;
    out[(size_t)(g0 + gl) * 256 + 128 + jx] =
        g_HNlast[(size_t)(g0 + gl) * 128 + jx];
  }
}

// ================= host =================
extern "C" void kernel_launch(void* const* d_in, const int* in_sizes, int n_in,
                              void* d_out, int out_size) {
  const float* feat = (const float*)d_in[0];
  const float* cnt  = (const float*)d_in[1];
  const float* W_in = (const float*)d_in[2];
  const float* b_in = (const float*)d_in[3];
  const float* W_og = (const float*)d_in[4];
  const float* b_og = (const float*)d_in[5];
  const float* W_ih = (const float*)d_in[6];
  const float* b_ih = (const float*)d_in[7];
  const float* W_hh = (const float*)d_in[8];
  const float* b_hh = (const float*)d_in[9];
  const float* W_u  = (const float*)d_in[10];
  const float* W_v  = (const float*)d_in[11];
  const float* b_v  = (const float*)d_in[12];
  const float* w_e  = (const float*)d_in[13];
  const int*   src  = (const int*)d_in[14];
  const int*   dst  = (const int*)d_in[15];
  float* out = (float*)d_out;

  const int SM_FV = 2 * SG;
  const int SM_ALPHA = 2 * SG + 4608;
  static bool attr_done = false;
  if (!attr_done) {
    cudaFuncSetAttribute(k_yagg, cudaFuncAttributeMaxDynamicSharedMemorySize, SM_YAGG);
    cudaFuncSetAttribute(k_gates, cudaFuncAttributeMaxDynamicSharedMemorySize, SM_GATES);
    cudaFuncSetAttribute(k_fv, cudaFuncAttributeMaxDynamicSharedMemorySize, SM_FV);
    cudaFuncSetAttribute(k_alpha, cudaFuncAttributeMaxDynamicSharedMemorySize, SM_ALPHA);
    attr_done = true;
  }

  k_zero_adj<<<512, 256>>>();
  k_build_adj<<<NEDGE / 256, 256>>>(src, dst);
  k_pack<<<2048, 256>>>(feat, W_in, W_og, W_ih, W_hh, W_u, W_v,
                        b_in, b_og, b_ih, b_hh);

  k_yagg<<<dim3(NNODE / 128, 2), 256, SM_YAGG>>>();
  k_gates<<<dim3(512, 4), 256, SM_GATES>>>();
  k_fv<<<NGRAPH / 128, 128, SM_FV>>>(b_v);
  k_alpha<<<NNODE / 128, 256, SM_ALPHA>>>(cnt, w_e, out);
}

// round 13
// speedup vs baseline: 1.2129x; 1.2129x over previous
#include <cuda_runtime.h>
#include <cuda_fp16.h>
#include <cstdint>

#define NGRAPH 8192
#define NNODE (NGRAPH * 32)
#define NEDGE 524288

typedef __half h16;

// ================= static device scratch =================
__device__ __align__(16) h16  g_adjh[NGRAPH * 1024];   // fp16 counts
__device__ __align__(16) h16  g_featH[(size_t)NNODE * 128];
__device__ __align__(16) h16  g_AggH[(size_t)NNODE * 256];
__device__ __align__(16) h16  g_HNh[(size_t)NNODE * 128];
__device__ __align__(16) float g_HNlast[(size_t)NGRAPH * 128];
__device__ __align__(16) float g_FV[(size_t)NGRAPH * 128];
__device__ __align__(16) h16  g_Wio[256 * 128];
__device__ __align__(16) h16  g_Wg[512 * 384];
__device__ __align__(16) h16  g_Wu[128 * 128];
__device__ __align__(16) h16  g_Wv[128 * 128];
__device__ __align__(16) float g_biasY[256];
__device__ __align__(16) float g_biasG[512];

// ================= helpers =================
__device__ __forceinline__ uint32_t smem_to_u32(const void* p) {
  uint32_t a;
  asm("{ .reg .u64 tmp; cvta.to.shared.u64 tmp, %1; cvt.u32.u64 %0, tmp; }"
      : "=r"(a) : "l"(p));
  return a;
}
#define SWZ(off) ((off) ^ (((off) >> 3) & 0x70))

__device__ __forceinline__ void cp16(uint32_t dst, const void* src) {
  asm volatile("cp.async.cg.shared.global [%0], [%1], 16;" ::"r"(dst), "l"(src));
}
#define CP_COMMIT() asm volatile("cp.async.commit_group;" ::: "memory")
#define CP_WAIT(n) asm volatile("cp.async.wait_group %0;" ::"n"(n) : "memory")

__device__ __forceinline__ void ldsm_x4(uint32_t addr, uint32_t* r) {
  asm volatile("ldmatrix.sync.aligned.m8n8.x4.shared.b16 {%0,%1,%2,%3}, [%4];"
               : "=r"(r[0]), "=r"(r[1]), "=r"(r[2]), "=r"(r[3]) : "r"(addr));
}
__device__ __forceinline__ void ldsm_x4_t(uint32_t addr, uint32_t* r) {
  asm volatile("ldmatrix.sync.aligned.m8n8.x4.trans.shared.b16 {%0,%1,%2,%3}, [%4];"
               : "=r"(r[0]), "=r"(r[1]), "=r"(r[2]), "=r"(r[3]) : "r"(addr));
}
__device__ __forceinline__ void mma16816(float* d, const uint32_t* a,
                                         const uint32_t* b) {
  asm volatile(
      "mma.sync.aligned.m16n8k16.row.col.f32.f16.f16.f32 "
      "{%0,%1,%2,%3}, {%4,%5,%6,%7}, {%8,%9}, {%0,%1,%2,%3};"
      : "+f"(d[0]), "+f"(d[1]), "+f"(d[2]), "+f"(d[3])
      : "r"(a[0]), "r"(a[1]), "r"(a[2]), "r"(a[3]), "r"(b[0]), "r"(b[1]));
}

__device__ __forceinline__ float sigf(float x) { return 1.f / (1.f + __expf(-x)); }
__device__ __forceinline__ float tanh_fast(float x) {
  float e2x = __expf(2.f * x);
  return 1.f - 2.f / (e2x + 1.f);
}
__device__ __forceinline__ float h2f(h16 v) { return __half2float(v); }
__device__ __forceinline__ uint32_t pack2h(float a, float b) {
  __half2 h = __floats2half2_rn(a, b);
  return *(uint32_t*)&h;
}

// ================= adjacency (fp16 direct) =================
__global__ void k_zero_adj() {
  int i = blockIdx.x * blockDim.x + threadIdx.x;
  int stride = gridDim.x * blockDim.x;
  int4* p = (int4*)g_adjh;
  const int n4 = NGRAPH * 1024 * 2 / 16;
  int4 z = make_int4(0, 0, 0, 0);
  for (; i < n4; i += stride) p[i] = z;
}
__global__ void k_build_adj(const int* __restrict__ src, const int* __restrict__ dst) {
  int e = blockIdx.x * blockDim.x + threadIdx.x;
  if (e >= NEDGE) return;
  int d = dst[e];
  int s = src[e];
  int idx = ((d >> 5) << 10) + ((d & 31) << 5) + (s & 31);
  __half2 v = (idx & 1) ? __floats2half2_rn(0.f, 1.f)
                        : __floats2half2_rn(1.f, 0.f);
  atomicAdd(&((__half2*)g_adjh)[idx >> 1], v);
}

// ================= weight pack + feat convert =================
__global__ void k_pack(const float* __restrict__ feat,
                       const float* __restrict__ W_in, const float* __restrict__ W_og,
                       const float* __restrict__ W_ih, const float* __restrict__ W_hh,
                       const float* __restrict__ W_u, const float* __restrict__ W_v,
                       const float* __restrict__ b_in, const float* __restrict__ b_og,
                       const float* __restrict__ b_ih, const float* __restrict__ b_hh) {
  int i0 = blockIdx.x * 256 + threadIdx.x;
  int stride = gridDim.x * 256;
  {
    const float4* f4 = (const float4*)feat;
    const size_t n4 = (size_t)NNODE * 32;
    for (size_t i = i0; i < n4; i += stride) {
      float4 v = f4[i];
      __half2* dstp = (__half2*)&g_featH[i * 4];
      dstp[0] = __floats2half2_rn(v.x, v.y);
      dstp[1] = __floats2half2_rn(v.z, v.w);
    }
  }
  for (int i = i0; i < 256 * 128; i += stride) {
    int r = i >> 7, c = i & 127;
    float v = (r < 128) ? W_in[r * 128 + c] : W_og[(r - 128) * 128 + c];
    g_Wio[i] = __float2half_rn(v);
  }
  for (int i = i0; i < 512 * 384; i += stride) {
    int r = i / 384, c = i % 384;
    int blk = r >> 7, rr = r & 127;
    float v;
    if (blk == 0)      v = (c < 256) ? W_ih[rr * 256 + c] : W_hh[rr * 128 + (c - 256)];
    else if (blk == 1) v = (c < 256) ? W_ih[(128 + rr) * 256 + c] : W_hh[(128 + rr) * 128 + (c - 256)];
    else if (blk == 2) v = (c < 256) ? W_ih[(256 + rr) * 256 + c] : 0.f;
    else               v = (c < 256) ? 0.f : W_hh[(256 + rr) * 128 + (c - 256)];
    g_Wg[i] = __float2half_rn(v);
  }
  for (int i = i0; i < 128 * 128; i += stride) {
    g_Wu[i] = __float2half_rn(W_u[i]);
    g_Wv[i] = __float2half_rn(W_v[i]);
  }
  for (int i = i0; i < 256; i += stride)
    g_biasY[i] = (i < 128) ? b_in[i] : b_og[i - 128];
  for (int i = i0; i < 512; i += stride) {
    float v;
    if (i < 256)      v = b_ih[i] + b_hh[i];
    else if (i < 384) v = b_ih[i];
    else              v = b_hh[i - 128];
    g_biasG[i] = v;
  }
}

// ================= Y GEMM + tensorized aggregation (2 CTA/SM) ====
#define YSG 32768
#define Y_ADJ 65536
#define Y_RDEG (65536 + 10240)
#define SM_YAGG (65536 + 10240 + 512)

__global__ void __launch_bounds__(256, 2) k_yagg() {
  extern __shared__ __align__(1024) char smem[];
  const uint32_t sb = smem_to_u32(smem);
  const int tid = threadIdx.x;
  const int lid = tid & 31, wid = tid >> 5;
  const int m0 = blockIdx.x * 128;
  const int nb = blockIdx.y;
  const int g0 = m0 >> 5;
  const int wm0 = (wid & 3) * 32, wn0 = (wid >> 2) * 64;

  const h16* Bh = g_Wio + (size_t)nb * 128 * 128;
  float* rdeg = (float*)(smem + Y_RDEG);

  auto issue = [&](int kc, int s) {
    uint32_t base = sb + s * YSG;
#pragma unroll
    for (int i = 0; i < 4; i++) {
      int u = tid + 256 * i;
      int r = u >> 3, seg = u & 7;
      uint32_t d = SWZ(r * 128 + seg * 16);
      cp16(base + d, g_featH + (size_t)(m0 + r) * 128 + kc + seg * 8);
      cp16(base + 16384 + d, Bh + (size_t)r * 128 + kc + seg * 8);
    }
    CP_COMMIT();
  };

  issue(0, 0);
  issue(64, 1);

  const h16* adjg = g_adjh + ((size_t)g0 << 10);
#pragma unroll
  for (int i = 0; i < 16; i++) {
    int u = tid + 256 * i;
    int gl = u >> 10, rem = u & 1023;
    int n = rem >> 5, k = rem & 31;
    int row, col;
    if (nb == 0) { row = gl * 32 + n; col = k; }
    else { row = gl * 32 + k; col = n; }
    *(h16*)(smem + Y_ADJ + row * 80 + col * 2) = adjg[u];
  }
  __syncthreads();
  if (tid < 128) {
    float s = 0.f;
#pragma unroll
    for (int k = 0; k < 32; k++)
      s += h2f(*(h16*)(smem + Y_ADJ + tid * 80 + k * 2));
    rdeg[tid] = 1.f / fmaxf(s, 1.f);
  }

  float acc[2][8][4];
#pragma unroll
  for (int mi = 0; mi < 2; mi++)
#pragma unroll
    for (int ni = 0; ni < 8; ni++)
#pragma unroll
      for (int q = 0; q < 4; q++) acc[mi][ni][q] = 0.f;

  const int j = lid >> 3, rr = lid & 7;
#pragma unroll
  for (int c = 0; c < 2; c++) {
    if (c == 0) CP_WAIT(1); else CP_WAIT(0);
    __syncthreads();
    const uint32_t st = sb + c * YSG;
#pragma unroll
    for (int kk = 0; kk < 4; kk++) {
      uint32_t ah[2][4], bh[8][2];
#pragma unroll
      for (int mi = 0; mi < 2; mi++) {
        int row = wm0 + mi * 16 + (j & 1) * 8 + rr;
        int kb = kk * 32 + (j >> 1) * 16;
        ldsm_x4(st + SWZ(row * 128 + kb), ah[mi]);
      }
#pragma unroll
      for (int p = 0; p < 4; p++) {
        int n = wn0 + p * 16 + (j >> 1) * 8 + rr;
        int kb = kk * 32 + (j & 1) * 16;
        uint32_t t[4];
        ldsm_x4(st + 16384 + SWZ(n * 128 + kb), t);
        bh[2 * p][0] = t[0]; bh[2 * p][1] = t[1];
        bh[2 * p + 1][0] = t[2]; bh[2 * p + 1][1] = t[3];
      }
#pragma unroll
      for (int mi = 0; mi < 2; mi++)
#pragma unroll
        for (int ni = 0; ni < 8; ni++)
          mma16816(acc[mi][ni], ah[mi], bh[ni]);
    }
  }
  __syncthreads();

  const int gp = lid >> 2, tg = lid & 3;
#pragma unroll
  for (int mi = 0; mi < 2; mi++)
#pragma unroll
    for (int ni = 0; ni < 8; ni++) {
      int r = wm0 + mi * 16 + gp;
      int c = wn0 + ni * 8 + tg * 2;
      float b0 = g_biasY[nb * 128 + c], b1 = g_biasY[nb * 128 + c + 1];
      uint32_t tileo = (c >> 6) * 16384;
      *(uint32_t*)(smem + tileo + SWZ(r * 128 + (c & 63) * 2)) =
          pack2h(acc[mi][ni][0] + b0, acc[mi][ni][1] + b1);
      *(uint32_t*)(smem + tileo + SWZ((r + 8) * 128 + (c & 63) * 2)) =
          pack2h(acc[mi][ni][2] + b0, acc[mi][ni][3] + b1);
    }
  __syncthreads();

  {
    const int arow = wid * 16;
    const int krow0 = (wid >> 1) * 32;
    uint32_t af[2][4];
#pragma unroll
    for (int ks = 0; ks < 2; ks++) {
      uint32_t addr = sb + Y_ADJ + (arow + (j & 1) * 8 + rr) * 80 +
                      (j >> 1) * 16 + ks * 32;
      ldsm_x4(addr, af[ks]);
    }
    float accC[16][4];
#pragma unroll
    for (int nf = 0; nf < 16; nf++)
#pragma unroll
      for (int q = 0; q < 4; q++) accC[nf][q] = 0.f;
#pragma unroll
    for (int p = 0; p < 8; p++) {
#pragma unroll
      for (int ks = 0; ks < 2; ks++) {
        int krow = krow0 + ks * 16 + (j & 1) * 8 + rr;
        int c = p * 16 + (j >> 1) * 8;
        uint32_t t[4];
        ldsm_x4_t(sb + (c >> 6) * 16384 + SWZ(krow * 128 + (c & 63) * 2), t);
        mma16816(accC[2 * p], af[ks], t);
        mma16816(accC[2 * p + 1], af[ks], t + 2);
      }
    }
#pragma unroll
    for (int nf = 0; nf < 16; nf++) {
      int col = nf * 8 + tg * 2;
      int r0 = arow + gp, r1 = arow + gp + 8;
      float rd0 = rdeg[r0], rd1 = rdeg[r1];
      size_t o0 = (size_t)(m0 + r0) * 256 + nb * 128 + col;
      size_t o1 = (size_t)(m0 + r1) * 256 + nb * 128 + col;
      *(uint32_t*)&g_AggH[o0] = pack2h(accC[nf][0] * rd0, accC[nf][1] * rd0);
      *(uint32_t*)&g_AggH[o1] = pack2h(accC[nf][2] * rd1, accC[nf][3] * rd1);
    }
  }
}

// ========== gates: column-split, 3-stage single-sync pipeline (2 CTA/SM) ==
// grid (NNODE/64, 2): CTA = 64 rows x cols [nh*64, nh*64+64) of ALL 4 gates.
#define GA 0            // 3 x 8KB A stages
#define GB 24576        // 3 x 24KB B stages
#define SM_GATES 98304

__global__ void __launch_bounds__(256, 2) k_gates() {
  extern __shared__ __align__(1024) char smem[];
  const uint32_t sb = smem_to_u32(smem);
  const int tid = threadIdx.x;
  const int lid = tid & 31, wid = tid >> 5;
  const int m0 = blockIdx.x * 64;
  const int nh = blockIdx.y;
  const int cs = nh * 64;
  const int gate = wid >> 1;
  const int wm0g = (wid & 1) * 32;

  auto issueA = [&](int ch) {
    uint32_t base = sb + GA + (ch % 3) * 8192;
    const h16* src0;
    int ld, kk;
    if (ch < 4) { src0 = g_AggH; ld = 256; kk = ch * 64; }
    else { src0 = g_featH; ld = 128; kk = (ch - 4) * 64; }
#pragma unroll
    for (int i = 0; i < 2; i++) {
      int u = tid + 256 * i;
      int r = u >> 3, seg = u & 7;
      cp16(base + SWZ(r * 128 + seg * 16),
           src0 + (size_t)(m0 + r) * ld + kk + seg * 8);
    }
  };
  auto issueB = [&](int ch) {
    uint32_t base = sb + GB + (ch % 3) * 24576;
#pragma unroll
    for (int slot = 0; slot < 3; slot++) {
      int bg = (slot < 2) ? slot : (ch >= 4 ? 3 : 2);
#pragma unroll
      for (int i = 0; i < 2; i++) {
        int u = tid + 256 * i;
        int r = u >> 3, seg = u & 7;
        cp16(base + slot * 8192 + SWZ(r * 128 + seg * 16),
             g_Wg + (size_t)(bg * 128 + cs + r) * 384 + ch * 64 + seg * 8);
      }
    }
  };
  issueA(0); issueB(0); CP_COMMIT();
  issueA(1); issueB(1); CP_COMMIT();

  float acc[2][8][4];
#pragma unroll
  for (int mi = 0; mi < 2; mi++)
#pragma unroll
    for (int ni = 0; ni < 8; ni++)
#pragma unroll
      for (int q = 0; q < 4; q++) acc[mi][ni][q] = 0.f;

  const int j = lid >> 3, rr = lid & 7;
  for (int ch = 0; ch < 6; ch++) {
    if (ch < 5) CP_WAIT(1); else CP_WAIT(0);
    __syncthreads();
    if (ch + 2 < 6) { issueA(ch + 2); issueB(ch + 2); CP_COMMIT(); }
    bool active = (gate == 2) ? (ch < 4) : (gate == 3) ? (ch >= 4) : true;
    if (active) {
      const uint32_t abase = sb + GA + (ch % 3) * 8192;
      const uint32_t bbase =
          sb + GB + (ch % 3) * 24576 + ((gate < 2) ? gate : 2) * 8192;
#pragma unroll
      for (int kk = 0; kk < 4; kk++) {
        uint32_t ah[2][4], bh[8][2];
#pragma unroll
        for (int mi = 0; mi < 2; mi++) {
          int row = wm0g + mi * 16 + (j & 1) * 8 + rr;
          int kb = kk * 32 + (j >> 1) * 16;
          ldsm_x4(abase + SWZ(row * 128 + kb), ah[mi]);
        }
#pragma unroll
        for (int p = 0; p < 4; p++) {
          int n = p * 16 + (j >> 1) * 8 + rr;
          int kb = kk * 32 + (j & 1) * 16;
          uint32_t t[4];
          ldsm_x4(bbase + SWZ(n * 128 + kb), t);
          bh[2 * p][0] = t[0]; bh[2 * p][1] = t[1];
          bh[2 * p + 1][0] = t[2]; bh[2 * p + 1][1] = t[3];
        }
#pragma unroll
        for (int mi = 0; mi < 2; mi++)
#pragma unroll
          for (int ni = 0; ni < 8; ni++)
            mma16816(acc[mi][ni], ah[mi], bh[ni]);
      }
    }
  }
  __syncthreads();

  // ---- fused GRU in 2 col-halves (exchange via dead B region) ----
  float* sG = (float*)(smem + GB);   // 4 gates x 64 rows x 32 cols f32 = 32KB
  const int gp = lid >> 2, tg = lid & 3;
  const int fstage = (4 + nh) % 3;   // A stage holding feat chunk 4+nh
  for (int hc = 0; hc < 2; hc++) {
#pragma unroll
    for (int mi = 0; mi < 2; mi++)
#pragma unroll
      for (int nf = 0; nf < 4; nf++) {
        int ni = hc * 4 + nf;
        int c = nf * 8 + tg * 2;
        int r = wm0g + mi * 16 + gp;
        sG[(gate * 64 + r) * 32 + c] = acc[mi][ni][0];
        sG[(gate * 64 + r) * 32 + c + 1] = acc[mi][ni][1];
        sG[(gate * 64 + r + 8) * 32 + c] = acc[mi][ni][2];
        sG[(gate * 64 + r + 8) * 32 + c + 1] = acc[mi][ni][3];
      }
    __syncthreads();
    {
      const int row = tid >> 2, q = tid & 3;
      const int colbase = hc * 32 + q * 8;      // within 64-col slice
      const bool lastrow = (row & 31) == 31;
      __align__(16) h16 oh[8];
#pragma unroll
      for (int c2 = 0; c2 < 4; c2++) {
        uint32_t fh = *(uint32_t*)(smem + GA + fstage * 8192 +
                                   SWZ(row * 128 + (colbase + c2 * 2) * 2));
        float2 fvp = __half22float2(*(__half2*)&fh);
#pragma unroll
        for (int c1 = 0; c1 < 2; c1++) {
          int c = c2 * 2 + c1;
          int cc = q * 8 + c;                  // sG col index (0..31)
          int colg = cs + colbase + c;         // global col
          float r_ = sigf(sG[row * 32 + cc] + __ldg(&g_biasG[colg]));
          float z_ = sigf(sG[(64 + row) * 32 + cc] + __ldg(&g_biasG[128 + colg]));
          float is = sG[(128 + row) * 32 + cc] + __ldg(&g_biasG[256 + colg]);
          float hs = sG[(192 + row) * 32 + cc] + __ldg(&g_biasG[384 + colg]);
          float ng = tanh_fast(is + r_ * hs);
          float f = (c1 == 0) ? fvp.x : fvp.y;
          float hn = (1.f - z_) * ng + z_ * f;
          oh[c] = __float2half_rn(hn);
          if (lastrow)
            g_HNlast[(size_t)((m0 + row) >> 5) * 128 + colg] = hn;
        }
      }
      *(int4*)&g_HNh[(size_t)(m0 + row) * 128 + cs + colbase] = *(int4*)oh;
    }
    __syncthreads();
  }
}

// ================= FV GEMM (small, 128 thr) =================
#define SG 32768
__global__ void __launch_bounds__(128, 2) k_fv(const float* __restrict__ b_v) {
  extern __shared__ __align__(1024) char smem[];
  const uint32_t sb = smem_to_u32(smem);
  const int tid = threadIdx.x;
  const int lid = tid & 31, wid = tid >> 5;
  const int m0 = blockIdx.x * 128;
  const int wm0 = (wid & 1) * 64, wn0 = (wid >> 1) * 64;

  auto issue = [&](int kc, int s) {
    uint32_t base = sb + s * SG;
#pragma unroll
    for (int i = 0; i < 8; i++) {
      int u = tid + 128 * i;
      int r = u >> 3, seg = u & 7;
      uint32_t d = SWZ(r * 128 + seg * 16);
      cp16(base + d, g_HNh + ((size_t)(m0 + r) * 32 + 31) * 128 + kc + seg * 8);
      cp16(base + 16384 + d, g_Wv + (size_t)r * 128 + kc + seg * 8);
    }
    CP_COMMIT();
  };

  float acc[4][8][4];
#pragma unroll
  for (int mi = 0; mi < 4; mi++)
#pragma unroll
    for (int ni = 0; ni < 8; ni++)
#pragma unroll
      for (int q = 0; q < 4; q++) acc[mi][ni][q] = 0.f;

  issue(0, 0);
  issue(64, 1);
  const int j = lid >> 3, rr = lid & 7;
#pragma unroll
  for (int c = 0; c < 2; c++) {
    if (c == 0) CP_WAIT(1); else CP_WAIT(0);
    __syncthreads();
    const uint32_t st = sb + c * SG;
#pragma unroll
    for (int kk = 0; kk < 4; kk++) {
      uint32_t ah[4][4], bh[8][2];
#pragma unroll
      for (int mi = 0; mi < 4; mi++) {
        int row = wm0 + mi * 16 + (j & 1) * 8 + rr;
        int kb = kk * 32 + (j >> 1) * 16;
        ldsm_x4(st + SWZ(row * 128 + kb), ah[mi]);
      }
#pragma unroll
      for (int p = 0; p < 4; p++) {
        int n = wn0 + p * 16 + (j >> 1) * 8 + rr;
        int kb = kk * 32 + (j & 1) * 16;
        uint32_t t[4];
        ldsm_x4(st + 16384 + SWZ(n * 128 + kb), t);
        bh[2 * p][0] = t[0]; bh[2 * p][1] = t[1];
        bh[2 * p + 1][0] = t[2]; bh[2 * p + 1][1] = t[3];
      }
#pragma unroll
      for (int mi = 0; mi < 4; mi++)
#pragma unroll
        for (int ni = 0; ni < 8; ni++)
          mma16816(acc[mi][ni], ah[mi], bh[ni]);
    }
    __syncthreads();
  }
  const int gp = lid >> 2, tg = lid & 3;
#pragma unroll
  for (int mi = 0; mi < 4; mi++)
#pragma unroll
    for (int ni = 0; ni < 8; ni++) {
      int r0 = m0 + wm0 + mi * 16 + gp;
      int c = wn0 + ni * 8 + tg * 2;
      float b0 = b_v[c], b1 = b_v[c + 1];
      *(float2*)&g_FV[(size_t)r0 * 128 + c] =
          make_float2(acc[mi][ni][0] + b0, acc[mi][ni][1] + b1);
      *(float2*)&g_FV[(size_t)(r0 + 8) * 128 + c] =
          make_float2(acc[mi][ni][2] + b0, acc[mi][ni][3] + b1);
    }
}

// ================= U GEMM + attention + readout (2 CTA/SM) ======
__global__ void __launch_bounds__(256, 2) k_alpha(const float* __restrict__ cnt,
                                                  const float* __restrict__ we,
                                                  float* __restrict__ out) {
  extern __shared__ __align__(1024) char smem[];
  const uint32_t sb = smem_to_u32(smem);
  const int tid = threadIdx.x;
  const int lid = tid & 31, wid = tid >> 5;
  const int m0 = blockIdx.x * 128;
  const int g0 = m0 >> 5;
  const int wm0 = (wid & 3) * 32, wn0 = (wid >> 2) * 64;

  float* sFV = (float*)(smem + 2 * SG);
  float* swe = sFV + 512;
  float* scnt = swe + 128;
  float* sPart = scnt + 128;
  float* sAl = sPart + 256;

  auto issue = [&](int kc, int s) {
    uint32_t base = sb + s * SG;
#pragma unroll
    for (int i = 0; i < 4; i++) {
      int u = tid + 256 * i;
      int r = u >> 3, seg = u & 7;
      uint32_t d = SWZ(r * 128 + seg * 16);
      cp16(base + d, g_HNh + (size_t)(m0 + r) * 128 + kc + seg * 8);
      cp16(base + 16384 + d, g_Wu + (size_t)r * 128 + kc + seg * 8);
    }
    CP_COMMIT();
  };

  issue(0, 0);
  issue(64, 1);
#pragma unroll
  for (int i = 0; i < 2; i++) {
    int e = tid + 256 * i;
    sFV[e] = g_FV[(size_t)(g0 + (e >> 7)) * 128 + (e & 127)];
  }
  if (tid < 128) { swe[tid] = we[tid]; scnt[tid] = cnt[m0 + tid]; }

  float acc[2][8][4];
#pragma unroll
  for (int mi = 0; mi < 2; mi++)
#pragma unroll
    for (int ni = 0; ni < 8; ni++)
#pragma unroll
      for (int q = 0; q < 4; q++) acc[mi][ni][q] = 0.f;

  const int j = lid >> 3, rr = lid & 7;
#pragma unroll
  for (int c = 0; c < 2; c++) {
    if (c == 0) CP_WAIT(1); else CP_WAIT(0);
    __syncthreads();
    const uint32_t st = sb + c * SG;
#pragma unroll
    for (int kk = 0; kk < 4; kk++) {
      uint32_t ah[2][4], bh[8][2];
#pragma unroll
      for (int mi = 0; mi < 2; mi++) {
        int row = wm0 + mi * 16 + (j & 1) * 8 + rr;
        int kb = kk * 32 + (j >> 1) * 16;
        ldsm_x4(st + SWZ(row * 128 + kb), ah[mi]);
      }
#pragma unroll
      for (int p = 0; p < 4; p++) {
        int n = wn0 + p * 16 + (j >> 1) * 8 + rr;
        int kb = kk * 32 + (j & 1) * 16;
        uint32_t t[4];
        ldsm_x4(st + 16384 + SWZ(n * 128 + kb), t);
        bh[2 * p][0] = t[0]; bh[2 * p][1] = t[1];
        bh[2 * p + 1][0] = t[2]; bh[2 * p + 1][1] = t[3];
      }
#pragma unroll
      for (int mi = 0; mi < 2; mi++)
#pragma unroll
        for (int ni = 0; ni < 8; ni++)
          mma16816(acc[mi][ni], ah[mi], bh[ni]);
    }
  }
  __syncthreads();

  const int gp = lid >> 2, tg = lid & 3;
#pragma unroll
  for (int mi = 0; mi < 2; mi++) {
    int base = wm0 + mi * 16;
    int gl = base >> 5;
    float p0 = 0.f, p1 = 0.f;
#pragma unroll
    for (int ni = 0; ni < 8; ni++) {
      int jx = wn0 + ni * 8 + tg * 2;
      float fv0 = sFV[gl * 128 + jx], fv1 = sFV[gl * 128 + jx + 1];
      float w0 = swe[jx], w1 = swe[jx + 1];
      p0 += w0 * sigf(acc[mi][ni][0] + fv0) + w1 * sigf(acc[mi][ni][1] + fv1);
      p1 += w0 * sigf(acc[mi][ni][2] + fv0) + w1 * sigf(acc[mi][ni][3] + fv1);
    }
    p0 += __shfl_xor_sync(0xffffffffu, p0, 1);
    p0 += __shfl_xor_sync(0xffffffffu, p0, 2);
    p1 += __shfl_xor_sync(0xffffffffu, p1, 1);
    p1 += __shfl_xor_sync(0xffffffffu, p1, 2);
    if (tg == 0) {
      sPart[(wid >> 2) * 128 + base + gp] = p0;
      sPart[(wid >> 2) * 128 + base + gp + 8] = p1;
    }
  }
  __syncthreads();
  if (tid < 128) sAl[tid] = (sPart[tid] + sPart[128 + tid]) * scnt[tid];
  __syncthreads();

#pragma unroll
  for (int v = 0; v < 2; v++) {
    int idx = tid + v * 256;
    int gl = idx >> 7, jx = idx & 127;
    int stg = jx >> 6, cidx = jx & 63;
    float accg = 0.f;
#pragma unroll
    for (int n = 0; n < 32; n++) {
      float hn = h2f(*(h16*)(smem + stg * SG + SWZ((gl * 32 + n) * 128 + cidx * 2)));
      accg += hn * sAl[gl * 32 + n];
    }
    out[(size_t)(g0 + gl) * 256 + jx] = accg;
    out[(size_t)(g0 + gl) * 256 + 128 + jx] =
        g_HNlast[(size_t)(g0 + gl) * 128 + jx];
  }
}

// ================= host =================
extern "C" void kernel_launch(void* const* d_in, const int* in_sizes, int n_in,
                              void* d_out, int out_size) {
  const float* feat = (const float*)d_in[0];
  const float* cnt  = (const float*)d_in[1];
  const float* W_in = (const float*)d_in[2];
  const float* b_in = (const float*)d_in[3];
  const float* W_og = (const float*)d_in[4];
  const float* b_og = (const float*)d_in[5];
  const float* W_ih = (const float*)d_in[6];
  const float* b_ih = (const float*)d_in[7];
  const float* W_hh = (const float*)d_in[8];
  const float* b_hh = (const float*)d_in[9];
  const float* W_u  = (const float*)d_in[10];
  const float* W_v  = (const float*)d_in[11];
  const float* b_v  = (const float*)d_in[12];
  const float* w_e  = (const float*)d_in[13];
  const int*   src  = (const int*)d_in[14];
  const int*   dst  = (const int*)d_in[15];
  float* out = (float*)d_out;

  const int SM_FV = 2 * SG;
  const int SM_ALPHA = 2 * SG + 4608;
  static bool attr_done = false;
  if (!attr_done) {
    cudaFuncSetAttribute(k_yagg, cudaFuncAttributeMaxDynamicSharedMemorySize, SM_YAGG);
    cudaFuncSetAttribute(k_gates, cudaFuncAttributeMaxDynamicSharedMemorySize, SM_GATES);
    cudaFuncSetAttribute(k_fv, cudaFuncAttributeMaxDynamicSharedMemorySize, SM_FV);
    cudaFuncSetAttribute(k_alpha, cudaFuncAttributeMaxDynamicSharedMemorySize, SM_ALPHA);
    attr_done = true;
  }

  k_zero_adj<<<512, 256>>>();
  k_build_adj<<<NEDGE / 256, 256>>>(src, dst);
  k_pack<<<2048, 256>>>(feat, W_in, W_og, W_ih, W_hh, W_u, W_v,
                        b_in, b_og, b_ih, b_hh);

  k_yagg<<<dim3(NNODE / 128, 2), 256, SM_YAGG>>>();
  k_gates<<<dim3(NNODE / 64, 2), 256, SM_GATES>>>();
  k_fv<<<NGRAPH / 128, 128, SM_FV>>>(b_v);
  k_alpha<<<NNODE / 128, 256, SM_ALPHA>>>(cnt, w_e, out);
}

// round 14
// speedup vs baseline: 1.2152x; 1.0019x over previous
#include <cuda_runtime.h>
#include <cuda_fp16.h>
#include <cstdint>

#define NGRAPH 8192
#define NNODE (NGRAPH * 32)
#define NEDGE 524288

typedef __half h16;

// ================= static device scratch =================
__device__ __align__(16) h16  g_adjh[NGRAPH * 1024];   // fp16 counts
__device__ __align__(16) h16  g_featH[(size_t)NNODE * 128];
__device__ __align__(16) h16  g_AggH[(size_t)NNODE * 256];
__device__ __align__(16) h16  g_HNh[(size_t)NNODE * 128];
__device__ __align__(16) float g_HNlast[(size_t)NGRAPH * 128];
__device__ __align__(16) h16  g_Wio[256 * 128];
__device__ __align__(16) h16  g_Wg[512 * 384];
__device__ __align__(16) h16  g_Wu[128 * 128];
__device__ __align__(16) h16  g_Wv[128 * 128];
__device__ __align__(16) float g_biasY[256];
__device__ __align__(16) float g_biasG[512];

// ================= helpers =================
__device__ __forceinline__ uint32_t smem_to_u32(const void* p) {
  uint32_t a;
  asm("{ .reg .u64 tmp; cvta.to.shared.u64 tmp, %1; cvt.u32.u64 %0, tmp; }"
      : "=r"(a) : "l"(p));
  return a;
}
#define SWZ(off) ((off) ^ (((off) >> 3) & 0x70))

__device__ __forceinline__ void cp16(uint32_t dst, const void* src) {
  asm volatile("cp.async.cg.shared.global [%0], [%1], 16;" ::"r"(dst), "l"(src));
}
#define CP_COMMIT() asm volatile("cp.async.commit_group;" ::: "memory")
#define CP_WAIT(n) asm volatile("cp.async.wait_group %0;" ::"n"(n) : "memory")

__device__ __forceinline__ void ldsm_x4(uint32_t addr, uint32_t* r) {
  asm volatile("ldmatrix.sync.aligned.m8n8.x4.shared.b16 {%0,%1,%2,%3}, [%4];"
               : "=r"(r[0]), "=r"(r[1]), "=r"(r[2]), "=r"(r[3]) : "r"(addr));
}
__device__ __forceinline__ void ldsm_x4_t(uint32_t addr, uint32_t* r) {
  asm volatile("ldmatrix.sync.aligned.m8n8.x4.trans.shared.b16 {%0,%1,%2,%3}, [%4];"
               : "=r"(r[0]), "=r"(r[1]), "=r"(r[2]), "=r"(r[3]) : "r"(addr));
}
__device__ __forceinline__ void mma16816(float* d, const uint32_t* a,
                                         const uint32_t* b) {
  asm volatile(
      "mma.sync.aligned.m16n8k16.row.col.f32.f16.f16.f32 "
      "{%0,%1,%2,%3}, {%4,%5,%6,%7}, {%8,%9}, {%0,%1,%2,%3};"
      : "+f"(d[0]), "+f"(d[1]), "+f"(d[2]), "+f"(d[3])
      : "r"(a[0]), "r"(a[1]), "r"(a[2]), "r"(a[3]), "r"(b[0]), "r"(b[1]));
}

__device__ __forceinline__ float sigf(float x) { return 1.f / (1.f + __expf(-x)); }
__device__ __forceinline__ float tanh_fast(float x) {
  float e2x = __expf(2.f * x);
  return 1.f - 2.f / (e2x + 1.f);
}
__device__ __forceinline__ float h2f(h16 v) { return __half2float(v); }
__device__ __forceinline__ uint32_t pack2h(float a, float b) {
  __half2 h = __floats2half2_rn(a, b);
  return *(uint32_t*)&h;
}

// ================= adjacency build (zeroing merged into k_pack) ==========
__global__ void k_build_adj(const int* __restrict__ src, const int* __restrict__ dst) {
  int e = blockIdx.x * blockDim.x + threadIdx.x;
  if (e >= NEDGE) return;
  int d = dst[e];
  int s = src[e];
  int idx = ((d >> 5) << 10) + ((d & 31) << 5) + (s & 31);
  __half2 v = (idx & 1) ? __floats2half2_rn(0.f, 1.f)
                        : __floats2half2_rn(1.f, 0.f);
  atomicAdd(&((__half2*)g_adjh)[idx >> 1], v);
}

// ================= weight pack + feat convert + adj zero =================
__global__ void k_pack(const float* __restrict__ feat,
                       const float* __restrict__ W_in, const float* __restrict__ W_og,
                       const float* __restrict__ W_ih, const float* __restrict__ W_hh,
                       const float* __restrict__ W_u, const float* __restrict__ W_v,
                       const float* __restrict__ b_in, const float* __restrict__ b_og,
                       const float* __restrict__ b_ih, const float* __restrict__ b_hh) {
  int i0 = blockIdx.x * 256 + threadIdx.x;
  int stride = gridDim.x * 256;
  {
    int4* p = (int4*)g_adjh;
    const int n4 = NGRAPH * 1024 * 2 / 16;
    int4 z = make_int4(0, 0, 0, 0);
    for (int i = i0; i < n4; i += stride) p[i] = z;
  }
  {
    const float4* f4 = (const float4*)feat;
    const size_t n4 = (size_t)NNODE * 32;
    for (size_t i = i0; i < n4; i += stride) {
      float4 v = f4[i];
      __half2* dstp = (__half2*)&g_featH[i * 4];
      dstp[0] = __floats2half2_rn(v.x, v.y);
      dstp[1] = __floats2half2_rn(v.z, v.w);
    }
  }
  for (int i = i0; i < 256 * 128; i += stride) {
    int r = i >> 7, c = i & 127;
    float v = (r < 128) ? W_in[r * 128 + c] : W_og[(r - 128) * 128 + c];
    g_Wio[i] = __float2half_rn(v);
  }
  for (int i = i0; i < 512 * 384; i += stride) {
    int r = i / 384, c = i % 384;
    int blk = r >> 7, rr = r & 127;
    float v;
    if (blk == 0)      v = (c < 256) ? W_ih[rr * 256 + c] : W_hh[rr * 128 + (c - 256)];
    else if (blk == 1) v = (c < 256) ? W_ih[(128 + rr) * 256 + c] : W_hh[(128 + rr) * 128 + (c - 256)];
    else if (blk == 2) v = (c < 256) ? W_ih[(256 + rr) * 256 + c] : 0.f;
    else               v = (c < 256) ? 0.f : W_hh[(256 + rr) * 128 + (c - 256)];
    g_Wg[i] = __float2half_rn(v);
  }
  for (int i = i0; i < 128 * 128; i += stride) {
    g_Wu[i] = __float2half_rn(W_u[i]);
    g_Wv[i] = __float2half_rn(W_v[i]);
  }
  for (int i = i0; i < 256; i += stride)
    g_biasY[i] = (i < 128) ? b_in[i] : b_og[i - 128];
  for (int i = i0; i < 512; i += stride) {
    float v;
    if (i < 256)      v = b_ih[i] + b_hh[i];
    else if (i < 384) v = b_ih[i];
    else              v = b_hh[i - 128];
    g_biasG[i] = v;
  }
}

// ================= Y GEMM + tensorized aggregation (2 CTA/SM) ====
#define YSG 32768
#define Y_ADJ 65536
#define Y_RDEG (65536 + 10240)
#define SM_YAGG (65536 + 10240 + 512)

__global__ void __launch_bounds__(256, 2) k_yagg() {
  extern __shared__ __align__(1024) char smem[];
  const uint32_t sb = smem_to_u32(smem);
  const int tid = threadIdx.x;
  const int lid = tid & 31, wid = tid >> 5;
  const int m0 = blockIdx.x * 128;
  const int nb = blockIdx.y;
  const int g0 = m0 >> 5;
  const int wm0 = (wid & 3) * 32, wn0 = (wid >> 2) * 64;

  const h16* Bh = g_Wio + (size_t)nb * 128 * 128;
  float* rdeg = (float*)(smem + Y_RDEG);

  auto issue = [&](int kc, int s) {
    uint32_t base = sb + s * YSG;
#pragma unroll
    for (int i = 0; i < 4; i++) {
      int u = tid + 256 * i;
      int r = u >> 3, seg = u & 7;
      uint32_t d = SWZ(r * 128 + seg * 16);
      cp16(base + d, g_featH + (size_t)(m0 + r) * 128 + kc + seg * 8);
      cp16(base + 16384 + d, Bh + (size_t)r * 128 + kc + seg * 8);
    }
    CP_COMMIT();
  };

  issue(0, 0);
  issue(64, 1);

  const h16* adjg = g_adjh + ((size_t)g0 << 10);
#pragma unroll
  for (int i = 0; i < 16; i++) {
    int u = tid + 256 * i;
    int gl = u >> 10, rem = u & 1023;
    int n = rem >> 5, k = rem & 31;
    int row, col;
    if (nb == 0) { row = gl * 32 + n; col = k; }
    else { row = gl * 32 + k; col = n; }
    *(h16*)(smem + Y_ADJ + row * 80 + col * 2) = adjg[u];
  }
  __syncthreads();
  if (tid < 128) {
    float s = 0.f;
#pragma unroll
    for (int k = 0; k < 32; k++)
      s += h2f(*(h16*)(smem + Y_ADJ + tid * 80 + k * 2));
    rdeg[tid] = 1.f / fmaxf(s, 1.f);
  }

  float acc[2][8][4];
#pragma unroll
  for (int mi = 0; mi < 2; mi++)
#pragma unroll
    for (int ni = 0; ni < 8; ni++)
#pragma unroll
      for (int q = 0; q < 4; q++) acc[mi][ni][q] = 0.f;

  const int j = lid >> 3, rr = lid & 7;
#pragma unroll
  for (int c = 0; c < 2; c++) {
    if (c == 0) CP_WAIT(1); else CP_WAIT(0);
    __syncthreads();
    const uint32_t st = sb + c * YSG;
#pragma unroll
    for (int kk = 0; kk < 4; kk++) {
      uint32_t ah[2][4], bh[8][2];
#pragma unroll
      for (int mi = 0; mi < 2; mi++) {
        int row = wm0 + mi * 16 + (j & 1) * 8 + rr;
        int kb = kk * 32 + (j >> 1) * 16;
        ldsm_x4(st + SWZ(row * 128 + kb), ah[mi]);
      }
#pragma unroll
      for (int p = 0; p < 4; p++) {
        int n = wn0 + p * 16 + (j >> 1) * 8 + rr;
        int kb = kk * 32 + (j & 1) * 16;
        uint32_t t[4];
        ldsm_x4(st + 16384 + SWZ(n * 128 + kb), t);
        bh[2 * p][0] = t[0]; bh[2 * p][1] = t[1];
        bh[2 * p + 1][0] = t[2]; bh[2 * p + 1][1] = t[3];
      }
#pragma unroll
      for (int mi = 0; mi < 2; mi++)
#pragma unroll
        for (int ni = 0; ni < 8; ni++)
          mma16816(acc[mi][ni], ah[mi], bh[ni]);
    }
  }
  __syncthreads();

  const int gp = lid >> 2, tg = lid & 3;
#pragma unroll
  for (int mi = 0; mi < 2; mi++)
#pragma unroll
    for (int ni = 0; ni < 8; ni++) {
      int r = wm0 + mi * 16 + gp;
      int c = wn0 + ni * 8 + tg * 2;
      float b0 = g_biasY[nb * 128 + c], b1 = g_biasY[nb * 128 + c + 1];
      uint32_t tileo = (c >> 6) * 16384;
      *(uint32_t*)(smem + tileo + SWZ(r * 128 + (c & 63) * 2)) =
          pack2h(acc[mi][ni][0] + b0, acc[mi][ni][1] + b1);
      *(uint32_t*)(smem + tileo + SWZ((r + 8) * 128 + (c & 63) * 2)) =
          pack2h(acc[mi][ni][2] + b0, acc[mi][ni][3] + b1);
    }
  __syncthreads();

  {
    const int arow = wid * 16;
    const int krow0 = (wid >> 1) * 32;
    uint32_t af[2][4];
#pragma unroll
    for (int ks = 0; ks < 2; ks++) {
      uint32_t addr = sb + Y_ADJ + (arow + (j & 1) * 8 + rr) * 80 +
                      (j >> 1) * 16 + ks * 32;
      ldsm_x4(addr, af[ks]);
    }
    float accC[16][4];
#pragma unroll
    for (int nf = 0; nf < 16; nf++)
#pragma unroll
      for (int q = 0; q < 4; q++) accC[nf][q] = 0.f;
#pragma unroll
    for (int p = 0; p < 8; p++) {
#pragma unroll
      for (int ks = 0; ks < 2; ks++) {
        int krow = krow0 + ks * 16 + (j & 1) * 8 + rr;
        int c = p * 16 + (j >> 1) * 8;
        uint32_t t[4];
        ldsm_x4_t(sb + (c >> 6) * 16384 + SWZ(krow * 128 + (c & 63) * 2), t);
        mma16816(accC[2 * p], af[ks], t);
        mma16816(accC[2 * p + 1], af[ks], t + 2);
      }
    }
#pragma unroll
    for (int nf = 0; nf < 16; nf++) {
      int col = nf * 8 + tg * 2;
      int r0 = arow + gp, r1 = arow + gp + 8;
      float rd0 = rdeg[r0], rd1 = rdeg[r1];
      size_t o0 = (size_t)(m0 + r0) * 256 + nb * 128 + col;
      size_t o1 = (size_t)(m0 + r1) * 256 + nb * 128 + col;
      *(uint32_t*)&g_AggH[o0] = pack2h(accC[nf][0] * rd0, accC[nf][1] * rd0);
      *(uint32_t*)&g_AggH[o1] = pack2h(accC[nf][2] * rd1, accC[nf][3] * rd1);
    }
  }
}

// ========== gates: column-split, 3-stage pipeline, single-pass GRU ========
#define GA 0            // 3 x 8KB A stages
#define GB 24576        // 3 x 24KB B stages
#define G_BIAS 98304
#define SM_GATES (98304 + 2048)

__global__ void __launch_bounds__(256, 2) k_gates() {
  extern __shared__ __align__(1024) char smem[];
  const uint32_t sb = smem_to_u32(smem);
  float* sbias = (float*)(smem + G_BIAS);
  const int tid = threadIdx.x;
  const int lid = tid & 31, wid = tid >> 5;
  const int m0 = blockIdx.x * 64;
  const int nh = blockIdx.y;
  const int cs = nh * 64;
  const int gate = wid >> 1;
  const int wm0g = (wid & 1) * 32;

  auto issueA = [&](int ch) {
    uint32_t base = sb + GA + (ch % 3) * 8192;
    const h16* src0;
    int ld, kk;
    if (ch < 4) { src0 = g_AggH; ld = 256; kk = ch * 64; }
    else { src0 = g_featH; ld = 128; kk = (ch - 4) * 64; }
#pragma unroll
    for (int i = 0; i < 2; i++) {
      int u = tid + 256 * i;
      int r = u >> 3, seg = u & 7;
      cp16(base + SWZ(r * 128 + seg * 16),
           src0 + (size_t)(m0 + r) * ld + kk + seg * 8);
    }
  };
  auto issueB = [&](int ch) {
    uint32_t base = sb + GB + (ch % 3) * 24576;
#pragma unroll
    for (int slot = 0; slot < 3; slot++) {
      int bg = (slot < 2) ? slot : (ch >= 4 ? 3 : 2);
#pragma unroll
      for (int i = 0; i < 2; i++) {
        int u = tid + 256 * i;
        int r = u >> 3, seg = u & 7;
        cp16(base + slot * 8192 + SWZ(r * 128 + seg * 16),
             g_Wg + (size_t)(bg * 128 + cs + r) * 384 + ch * 64 + seg * 8);
      }
    }
  };
  issueA(0); issueB(0); CP_COMMIT();
  issueA(1); issueB(1); CP_COMMIT();
  for (int i = tid; i < 512; i += 256) sbias[i] = g_biasG[i];

  float acc[2][8][4];
#pragma unroll
  for (int mi = 0; mi < 2; mi++)
#pragma unroll
    for (int ni = 0; ni < 8; ni++)
#pragma unroll
      for (int q = 0; q < 4; q++) acc[mi][ni][q] = 0.f;

  const int j = lid >> 3, rr = lid & 7;
  for (int ch = 0; ch < 6; ch++) {
    if (ch < 5) CP_WAIT(1); else CP_WAIT(0);
    __syncthreads();
    if (ch + 2 < 6) { issueA(ch + 2); issueB(ch + 2); CP_COMMIT(); }
    bool active = (gate == 2) ? (ch < 4) : (gate == 3) ? (ch >= 4) : true;
    if (active) {
      const uint32_t abase = sb + GA + (ch % 3) * 8192;
      const uint32_t bbase =
          sb + GB + (ch % 3) * 24576 + ((gate < 2) ? gate : 2) * 8192;
#pragma unroll
      for (int kk = 0; kk < 4; kk++) {
        uint32_t ah[2][4], bh[8][2];
#pragma unroll
        for (int mi = 0; mi < 2; mi++) {
          int row = wm0g + mi * 16 + (j & 1) * 8 + rr;
          int kb = kk * 32 + (j >> 1) * 16;
          ldsm_x4(abase + SWZ(row * 128 + kb), ah[mi]);
        }
#pragma unroll
        for (int p = 0; p < 4; p++) {
          int n = p * 16 + (j >> 1) * 8 + rr;
          int kb = kk * 32 + (j & 1) * 16;
          uint32_t t[4];
          ldsm_x4(bbase + SWZ(n * 128 + kb), t);
          bh[2 * p][0] = t[0]; bh[2 * p][1] = t[1];
          bh[2 * p + 1][0] = t[2]; bh[2 * p + 1][1] = t[3];
        }
#pragma unroll
        for (int mi = 0; mi < 2; mi++)
#pragma unroll
          for (int ni = 0; ni < 8; ni++)
            mma16816(acc[mi][ni], ah[mi], bh[ni]);
      }
    }
  }
  __syncthreads();

  // ---- single-pass GRU: sG [4 gates][64 rows][stride 66] in dead B region
  float* sG = (float*)(smem + GB);   // 256*66*4 = 67584 B <= 72KB
  const int gp = lid >> 2, tg = lid & 3;
#pragma unroll
  for (int mi = 0; mi < 2; mi++)
#pragma unroll
    for (int ni = 0; ni < 8; ni++) {
      int r = wm0g + mi * 16 + gp;
      int c = ni * 8 + tg * 2;
      sG[(gate * 64 + r) * 66 + c] = acc[mi][ni][0];
      sG[(gate * 64 + r) * 66 + c + 1] = acc[mi][ni][1];
      sG[(gate * 64 + r + 8) * 66 + c] = acc[mi][ni][2];
      sG[(gate * 64 + r + 8) * 66 + c + 1] = acc[mi][ni][3];
    }
  __syncthreads();

  {
    const int row = tid >> 2, q = tid & 3;      // 16 cols per thread
    const int grow = m0 + row;
    const bool lastrow = (grow & 31) == 31;
    const int fstage = (4 + nh) % 3;
    __align__(16) h16 oh[16];
#pragma unroll
    for (int c2 = 0; c2 < 8; c2++) {
      int lc = q * 16 + c2 * 2;                 // local col within 64-slice
      uint32_t fh = *(uint32_t*)(smem + GA + fstage * 8192 +
                                 SWZ(row * 128 + lc * 2));
      float2 fvp = __half22float2(*(__half2*)&fh);
#pragma unroll
      for (int c1 = 0; c1 < 2; c1++) {
        int lcc = lc + c1;
        int colg = cs + lcc;
        float r_ = sigf(sG[row * 66 + lcc] + sbias[colg]);
        float z_ = sigf(sG[(64 + row) * 66 + lcc] + sbias[128 + colg]);
        float is = sG[(128 + row) * 66 + lcc] + sbias[256 + colg];
        float hs = sG[(192 + row) * 66 + lcc] + sbias[384 + colg];
        float ng = tanh_fast(is + r_ * hs);
        float f = (c1 == 0) ? fvp.x : fvp.y;
        float hn = (1.f - z_) * ng + z_ * f;
        oh[c2 * 2 + c1] = __float2half_rn(hn);
        if (lastrow) g_HNlast[(size_t)(grow >> 5) * 128 + colg] = hn;
      }
    }
    int4* dst = (int4*)&g_HNh[(size_t)grow * 128 + cs + q * 16];
    dst[0] = ((int4*)oh)[0];
    dst[1] = ((int4*)oh)[1];
  }
}

// ========= U GEMM + FV + attention + readout (2 CTA/SM, fv fused) =========
#define SG 32768
#define A_MISC (2 * SG)
#define A_WV (2 * SG + 6656)
#define SM_ALPHA (A_WV + 32768)

__global__ void __launch_bounds__(256, 2) k_alpha(const float* __restrict__ cnt,
                                                  const float* __restrict__ we,
                                                  const float* __restrict__ b_v,
                                                  float* __restrict__ out) {
  extern __shared__ __align__(1024) char smem[];
  const uint32_t sb = smem_to_u32(smem);
  const int tid = threadIdx.x;
  const int lid = tid & 31, wid = tid >> 5;
  const int m0 = blockIdx.x * 128;
  const int g0 = m0 >> 5;
  const int wm0 = (wid & 3) * 32, wn0 = (wid >> 2) * 64;

  float* sFV = (float*)(smem + A_MISC);   // [4][128]
  float* swe = sFV + 512;
  float* scnt = swe + 128;
  float* sPart = scnt + 128;              // [2][128]
  float* sAl = sPart + 256;               // [128]
  float* sLast = sAl + 128;               // [4][128] f32

  auto issue = [&](int kc, int s) {
    uint32_t base = sb + s * SG;
#pragma unroll
    for (int i = 0; i < 4; i++) {
      int u = tid + 256 * i;
      int r = u >> 3, seg = u & 7;
      uint32_t d = SWZ(r * 128 + seg * 16);
      cp16(base + d, g_HNh + (size_t)(m0 + r) * 128 + kc + seg * 8);
      cp16(base + 16384 + d, g_Wu + (size_t)r * 128 + kc + seg * 8);
    }
  };

  // group0: chunk0 + Wv; group1: chunk1
  issue(0, 0);
#pragma unroll
  for (int i = 0; i < 8; i++) {
    int u = tid + 256 * i;
    cp16(sb + A_WV + u * 16, g_Wv + u * 8);
  }
  CP_COMMIT();
  issue(64, 1);
  CP_COMMIT();

  if (tid < 128) { swe[tid] = we[tid]; scnt[tid] = cnt[m0 + tid]; }
#pragma unroll
  for (int i = 0; i < 2; i++) {
    int e = tid + 256 * i;
    sLast[e] = g_HNlast[(size_t)g0 * 128 + e];
  }

  float acc[2][8][4];
#pragma unroll
  for (int mi = 0; mi < 2; mi++)
#pragma unroll
    for (int ni = 0; ni < 8; ni++)
#pragma unroll
      for (int q = 0; q < 4; q++) acc[mi][ni][q] = 0.f;

  const int j = lid >> 3, rr = lid & 7;
#pragma unroll
  for (int c = 0; c < 2; c++) {
    if (c == 0) CP_WAIT(1); else CP_WAIT(0);
    __syncthreads();
    const uint32_t st = sb + c * SG;
#pragma unroll
    for (int kk = 0; kk < 4; kk++) {
      uint32_t ah[2][4], bh[8][2];
#pragma unroll
      for (int mi = 0; mi < 2; mi++) {
        int row = wm0 + mi * 16 + (j & 1) * 8 + rr;
        int kb = kk * 32 + (j >> 1) * 16;
        ldsm_x4(st + SWZ(row * 128 + kb), ah[mi]);
      }
#pragma unroll
      for (int p = 0; p < 4; p++) {
        int n = wn0 + p * 16 + (j >> 1) * 8 + rr;
        int kb = kk * 32 + (j & 1) * 16;
        uint32_t t[4];
        ldsm_x4(st + 16384 + SWZ(n * 128 + kb), t);
        bh[2 * p][0] = t[0]; bh[2 * p][1] = t[1];
        bh[2 * p + 1][0] = t[2]; bh[2 * p + 1][1] = t[3];
      }
#pragma unroll
      for (int mi = 0; mi < 2; mi++)
#pragma unroll
        for (int ni = 0; ni < 8; ni++)
          mma16816(acc[mi][ni], ah[mi], bh[ni]);
    }
  }
  __syncthreads();

  // ---- FV = HNlast(f32) . Wv^T + b_v ----
#pragma unroll
  for (int e2 = 0; e2 < 2; e2++) {
    int e = tid + 256 * e2;
    int gl = e >> 7, jx = e & 127;
    const __half2* wv = (const __half2*)(smem + A_WV + jx * 256);
    const float* hl = sLast + gl * 128;
    float s = b_v[jx];
#pragma unroll 8
    for (int kk = 0; kk < 64; kk++) {
      int k2 = (kk + jx) & 63;
      float2 w = __half22float2(wv[k2]);
      s += hl[2 * k2] * w.x + hl[2 * k2 + 1] * w.y;
    }
    sFV[e] = s;
  }
  __syncthreads();

  // ---- attention partials ----
  const int gp = lid >> 2, tg = lid & 3;
#pragma unroll
  for (int mi = 0; mi < 2; mi++) {
    int base = wm0 + mi * 16;
    int gl = base >> 5;
    float p0 = 0.f, p1 = 0.f;
#pragma unroll
    for (int ni = 0; ni < 8; ni++) {
      int jx = wn0 + ni * 8 + tg * 2;
      float fv0 = sFV[gl * 128 + jx], fv1 = sFV[gl * 128 + jx + 1];
      float w0 = swe[jx], w1 = swe[jx + 1];
      p0 += w0 * sigf(acc[mi][ni][0] + fv0) + w1 * sigf(acc[mi][ni][1] + fv1);
      p1 += w0 * sigf(acc[mi][ni][2] + fv0) + w1 * sigf(acc[mi][ni][3] + fv1);
    }
    p0 += __shfl_xor_sync(0xffffffffu, p0, 1);
    p0 += __shfl_xor_sync(0xffffffffu, p0, 2);
    p1 += __shfl_xor_sync(0xffffffffu, p1, 1);
    p1 += __shfl_xor_sync(0xffffffffu, p1, 2);
    if (tg == 0) {
      sPart[(wid >> 2) * 128 + base + gp] = p0;
      sPart[(wid >> 2) * 128 + base + gp + 8] = p1;
    }
  }
  __syncthreads();
  if (tid < 128) sAl[tid] = (sPart[tid] + sPart[128 + tid]) * scnt[tid];
  __syncthreads();

  // ---- readout: 1 col-pair per thread, __half2 loads ----
  {
    int gl = tid >> 6, jp = tid & 63;
    int col0 = 2 * jp;
    int stg = col0 >> 6, cl = col0 & 63;
    float a0 = 0.f, a1 = 0.f;
#pragma unroll
    for (int n = 0; n < 32; n++) {
      uint32_t hv = *(uint32_t*)(smem + stg * SG +
                                 SWZ((gl * 32 + n) * 128 + cl * 2));
      float2 h = __half22float2(*(__half2*)&hv);
      float al = sAl[gl * 32 + n];
      a0 += h.x * al;
      a1 += h.y * al;
    }
    size_t ob = (size_t)(g0 + gl) * 256;
    *(float2*)&out[ob + col0] = make_float2(a0, a1);
    *(float2*)&out[ob + 128 + col0] =
        make_float2(sLast[gl * 128 + col0], sLast[gl * 128 + col0 + 1]);
  }
}

// ================= host =================
extern "C" void kernel_launch(void* const* d_in, const int* in_sizes, int n_in,
                              void* d_out, int out_size) {
  const float* feat = (const float*)d_in[0];
  const float* cnt  = (const float*)d_in[1];
  const float* W_in = (const float*)d_in[2];
  const float* b_in = (const float*)d_in[3];
  const float* W_og = (const float*)d_in[4];
  const float* b_og = (const float*)d_in[5];
  const float* W_ih = (const float*)d_in[6];
  const float* b_ih = (const float*)d_in[7];
  const float* W_hh = (const float*)d_in[8];
  const float* b_hh = (const float*)d_in[9];
  const float* W_u  = (const float*)d_in[10];
  const float* W_v  = (const float*)d_in[11];
  const float* b_v  = (const float*)d_in[12];
  const float* w_e  = (const float*)d_in[13];
  const int*   src  = (const int*)d_in[14];
  const int*   dst  = (const int*)d_in[15];
  float* out = (float*)d_out;

  static bool attr_done = false;
  if (!attr_done) {
    cudaFuncSetAttribute(k_yagg, cudaFuncAttributeMaxDynamicSharedMemorySize, SM_YAGG);
    cudaFuncSetAttribute(k_gates, cudaFuncAttributeMaxDynamicSharedMemorySize, SM_GATES);
    cudaFuncSetAttribute(k_alpha, cudaFuncAttributeMaxDynamicSharedMemorySize, SM_ALPHA);
    attr_done = true;
  }

  k_pack<<<2048, 256>>>(feat, W_in, W_og, W_ih, W_hh, W_u, W_v,
                        b_in, b_og, b_ih, b_hh);
  k_build_adj<<<NEDGE / 256, 256>>>(src, dst);

  k_yagg<<<dim3(NNODE / 128, 2), 256, SM_YAGG>>>();
  k_gates<<<dim3(NNODE / 64, 2), 256, SM_GATES>>>();
  k_alpha<<<NNODE / 128, 256, SM_ALPHA>>>(cnt, w_e, b_v, out);
}

// round 15
// speedup vs baseline: 1.2639x; 1.0400x over previous
#include <cuda_runtime.h>
#include <cuda_fp16.h>
#include <cstdint>

#define NGRAPH 8192
#define NNODE (NGRAPH * 32)
#define NEDGE 524288

typedef __half h16;

// ================= static device scratch =================
__device__ __align__(16) h16  g_adjh[NGRAPH * 1024];   // fp16 counts
__device__ __align__(16) h16  g_featH[(size_t)NNODE * 128];
__device__ __align__(16) h16  g_AggH[(size_t)NNODE * 256];
__device__ __align__(16) h16  g_HNh[(size_t)NNODE * 128];
__device__ __align__(16) float g_HNlast[(size_t)NGRAPH * 128];
__device__ __align__(16) h16  g_Wio[256 * 128];
__device__ __align__(16) h16  g_Wg[512 * 384];
__device__ __align__(16) h16  g_Wu[128 * 128];
__device__ __align__(16) h16  g_Wv[128 * 128];
__device__ __align__(16) float g_biasY[256];
__device__ __align__(16) float g_biasG[512];

// ================= helpers =================
__device__ __forceinline__ uint32_t smem_to_u32(const void* p) {
  uint32_t a;
  asm("{ .reg .u64 tmp; cvta.to.shared.u64 tmp, %1; cvt.u32.u64 %0, tmp; }"
      : "=r"(a) : "l"(p));
  return a;
}
#define SWZ(off) ((off) ^ (((off) >> 3) & 0x70))

__device__ __forceinline__ void cp16(uint32_t dst, const void* src) {
  asm volatile("cp.async.cg.shared.global [%0], [%1], 16;" ::"r"(dst), "l"(src));
}
#define CP_COMMIT() asm volatile("cp.async.commit_group;" ::: "memory")
#define CP_WAIT(n) asm volatile("cp.async.wait_group %0;" ::"n"(n) : "memory")

__device__ __forceinline__ void ldsm_x4(uint32_t addr, uint32_t* r) {
  asm volatile("ldmatrix.sync.aligned.m8n8.x4.shared.b16 {%0,%1,%2,%3}, [%4];"
               : "=r"(r[0]), "=r"(r[1]), "=r"(r[2]), "=r"(r[3]) : "r"(addr));
}
__device__ __forceinline__ void ldsm_x4_t(uint32_t addr, uint32_t* r) {
  asm volatile("ldmatrix.sync.aligned.m8n8.x4.trans.shared.b16 {%0,%1,%2,%3}, [%4];"
               : "=r"(r[0]), "=r"(r[1]), "=r"(r[2]), "=r"(r[3]) : "r"(addr));
}
__device__ __forceinline__ void mma16816(float* d, const uint32_t* a,
                                         const uint32_t* b) {
  asm volatile(
      "mma.sync.aligned.m16n8k16.row.col.f32.f16.f16.f32 "
      "{%0,%1,%2,%3}, {%4,%5,%6,%7}, {%8,%9}, {%0,%1,%2,%3};"
      : "+f"(d[0]), "+f"(d[1]), "+f"(d[2]), "+f"(d[3])
      : "r"(a[0]), "r"(a[1]), "r"(a[2]), "r"(a[3]), "r"(b[0]), "r"(b[1]));
}

__device__ __forceinline__ float sigf(float x) { return 1.f / (1.f + __expf(-x)); }
__device__ __forceinline__ float tanh_fast(float x) {
  float e2x = __expf(2.f * x);
  return 1.f - 2.f / (e2x + 1.f);
}
__device__ __forceinline__ float h2f(h16 v) { return __half2float(v); }
__device__ __forceinline__ uint32_t pack2h(float a, float b) {
  __half2 h = __floats2half2_rn(a, b);
  return *(uint32_t*)&h;
}

// ================= adjacency build (zeroing merged into k_pack) ==========
__global__ void k_build_adj(const int* __restrict__ src, const int* __restrict__ dst) {
  int e = blockIdx.x * blockDim.x + threadIdx.x;
  if (e >= NEDGE) return;
  int d = dst[e];
  int s = src[e];
  int idx = ((d >> 5) << 10) + ((d & 31) << 5) + (s & 31);
  __half2 v = (idx & 1) ? __floats2half2_rn(0.f, 1.f)
                        : __floats2half2_rn(1.f, 0.f);
  atomicAdd(&((__half2*)g_adjh)[idx >> 1], v);
}

// ================= weight pack + feat convert + adj zero =================
__global__ void k_pack(const float* __restrict__ feat,
                       const float* __restrict__ W_in, const float* __restrict__ W_og,
                       const float* __restrict__ W_ih, const float* __restrict__ W_hh,
                       const float* __restrict__ W_u, const float* __restrict__ W_v,
                       const float* __restrict__ b_in, const float* __restrict__ b_og,
                       const float* __restrict__ b_ih, const float* __restrict__ b_hh) {
  int i0 = blockIdx.x * 256 + threadIdx.x;
  int stride = gridDim.x * 256;
  {
    int4* p = (int4*)g_adjh;
    const int n4 = NGRAPH * 1024 * 2 / 16;
    int4 z = make_int4(0, 0, 0, 0);
    for (int i = i0; i < n4; i += stride) p[i] = z;
  }
  {
    const float4* f4 = (const float4*)feat;
    const size_t n4 = (size_t)NNODE * 32;
    for (size_t i = i0; i < n4; i += stride) {
      float4 v = f4[i];
      __half2* dstp = (__half2*)&g_featH[i * 4];
      dstp[0] = __floats2half2_rn(v.x, v.y);
      dstp[1] = __floats2half2_rn(v.z, v.w);
    }
  }
  for (int i = i0; i < 256 * 128; i += stride) {
    int r = i >> 7, c = i & 127;
    float v = (r < 128) ? W_in[r * 128 + c] : W_og[(r - 128) * 128 + c];
    g_Wio[i] = __float2half_rn(v);
  }
  for (int i = i0; i < 512 * 384; i += stride) {
    int r = i / 384, c = i % 384;
    int blk = r >> 7, rr = r & 127;
    float v;
    if (blk == 0)      v = (c < 256) ? W_ih[rr * 256 + c] : W_hh[rr * 128 + (c - 256)];
    else if (blk == 1) v = (c < 256) ? W_ih[(128 + rr) * 256 + c] : W_hh[(128 + rr) * 128 + (c - 256)];
    else if (blk == 2) v = (c < 256) ? W_ih[(256 + rr) * 256 + c] : 0.f;
    else               v = (c < 256) ? 0.f : W_hh[(256 + rr) * 128 + (c - 256)];
    g_Wg[i] = __float2half_rn(v);
  }
  for (int i = i0; i < 128 * 128; i += stride) {
    g_Wu[i] = __float2half_rn(W_u[i]);
    g_Wv[i] = __float2half_rn(W_v[i]);
  }
  for (int i = i0; i < 256; i += stride)
    g_biasY[i] = (i < 128) ? b_in[i] : b_og[i - 128];
  for (int i = i0; i < 512; i += stride) {
    float v;
    if (i < 256)      v = b_ih[i] + b_hh[i];
    else if (i < 384) v = b_ih[i];
    else              v = b_hh[i - 128];
    g_biasG[i] = v;
  }
}

// ================= Y GEMM + tensorized aggregation (2 CTA/SM) ====
#define YSG 32768
#define Y_ADJ 65536
#define Y_RDEG (65536 + 10240)
#define SM_YAGG (65536 + 10240 + 512)

__global__ void __launch_bounds__(256, 2) k_yagg() {
  extern __shared__ __align__(1024) char smem[];
  const uint32_t sb = smem_to_u32(smem);
  const int tid = threadIdx.x;
  const int lid = tid & 31, wid = tid >> 5;
  const int m0 = blockIdx.x * 128;
  const int nb = blockIdx.y;
  const int g0 = m0 >> 5;
  const int wm0 = (wid & 3) * 32, wn0 = (wid >> 2) * 64;

  const h16* Bh = g_Wio + (size_t)nb * 128 * 128;
  float* rdeg = (float*)(smem + Y_RDEG);

  auto issue = [&](int kc, int s) {
    uint32_t base = sb + s * YSG;
#pragma unroll
    for (int i = 0; i < 4; i++) {
      int u = tid + 256 * i;
      int r = u >> 3, seg = u & 7;
      uint32_t d = SWZ(r * 128 + seg * 16);
      cp16(base + d, g_featH + (size_t)(m0 + r) * 128 + kc + seg * 8);
      cp16(base + 16384 + d, Bh + (size_t)r * 128 + kc + seg * 8);
    }
    CP_COMMIT();
  };

  issue(0, 0);
  issue(64, 1);

  const h16* adjg = g_adjh + ((size_t)g0 << 10);
#pragma unroll
  for (int i = 0; i < 16; i++) {
    int u = tid + 256 * i;
    int gl = u >> 10, rem = u & 1023;
    int n = rem >> 5, k = rem & 31;
    int row, col;
    if (nb == 0) { row = gl * 32 + n; col = k; }
    else { row = gl * 32 + k; col = n; }
    *(h16*)(smem + Y_ADJ + row * 80 + col * 2) = adjg[u];
  }
  __syncthreads();
  if (tid < 128) {
    float s = 0.f;
#pragma unroll
    for (int k = 0; k < 32; k++)
      s += h2f(*(h16*)(smem + Y_ADJ + tid * 80 + k * 2));
    rdeg[tid] = 1.f / fmaxf(s, 1.f);
  }

  float acc[2][8][4];
#pragma unroll
  for (int mi = 0; mi < 2; mi++)
#pragma unroll
    for (int ni = 0; ni < 8; ni++)
#pragma unroll
      for (int q = 0; q < 4; q++) acc[mi][ni][q] = 0.f;

  const int j = lid >> 3, rr = lid & 7;
#pragma unroll
  for (int c = 0; c < 2; c++) {
    if (c == 0) CP_WAIT(1); else CP_WAIT(0);
    __syncthreads();
    const uint32_t st = sb + c * YSG;
#pragma unroll
    for (int kk = 0; kk < 4; kk++) {
      uint32_t ah[2][4], bh[8][2];
#pragma unroll
      for (int mi = 0; mi < 2; mi++) {
        int row = wm0 + mi * 16 + (j & 1) * 8 + rr;
        int kb = kk * 32 + (j >> 1) * 16;
        ldsm_x4(st + SWZ(row * 128 + kb), ah[mi]);
      }
#pragma unroll
      for (int p = 0; p < 4; p++) {
        int n = wn0 + p * 16 + (j >> 1) * 8 + rr;
        int kb = kk * 32 + (j & 1) * 16;
        uint32_t t[4];
        ldsm_x4(st + 16384 + SWZ(n * 128 + kb), t);
        bh[2 * p][0] = t[0]; bh[2 * p][1] = t[1];
        bh[2 * p + 1][0] = t[2]; bh[2 * p + 1][1] = t[3];
      }
#pragma unroll
      for (int mi = 0; mi < 2; mi++)
#pragma unroll
        for (int ni = 0; ni < 8; ni++)
          mma16816(acc[mi][ni], ah[mi], bh[ni]);
    }
  }
  __syncthreads();

  const int gp = lid >> 2, tg = lid & 3;
#pragma unroll
  for (int mi = 0; mi < 2; mi++)
#pragma unroll
    for (int ni = 0; ni < 8; ni++) {
      int r = wm0 + mi * 16 + gp;
      int c = wn0 + ni * 8 + tg * 2;
      float b0 = g_biasY[nb * 128 + c], b1 = g_biasY[nb * 128 + c + 1];
      uint32_t tileo = (c >> 6) * 16384;
      *(uint32_t*)(smem + tileo + SWZ(r * 128 + (c & 63) * 2)) =
          pack2h(acc[mi][ni][0] + b0, acc[mi][ni][1] + b1);
      *(uint32_t*)(smem + tileo + SWZ((r + 8) * 128 + (c & 63) * 2)) =
          pack2h(acc[mi][ni][2] + b0, acc[mi][ni][3] + b1);
    }
  __syncthreads();

  {
    const int arow = wid * 16;
    const int krow0 = (wid >> 1) * 32;
    uint32_t af[2][4];
#pragma unroll
    for (int ks = 0; ks < 2; ks++) {
      uint32_t addr = sb + Y_ADJ + (arow + (j & 1) * 8 + rr) * 80 +
                      (j >> 1) * 16 + ks * 32;
      ldsm_x4(addr, af[ks]);
    }
    float accC[16][4];
#pragma unroll
    for (int nf = 0; nf < 16; nf++)
#pragma unroll
      for (int q = 0; q < 4; q++) accC[nf][q] = 0.f;
#pragma unroll
    for (int p = 0; p < 8; p++) {
#pragma unroll
      for (int ks = 0; ks < 2; ks++) {
        int krow = krow0 + ks * 16 + (j & 1) * 8 + rr;
        int c = p * 16 + (j >> 1) * 8;
        uint32_t t[4];
        ldsm_x4_t(sb + (c >> 6) * 16384 + SWZ(krow * 128 + (c & 63) * 2), t);
        mma16816(accC[2 * p], af[ks], t);
        mma16816(accC[2 * p + 1], af[ks], t + 2);
      }
    }
#pragma unroll
    for (int nf = 0; nf < 16; nf++) {
      int col = nf * 8 + tg * 2;
      int r0 = arow + gp, r1 = arow + gp + 8;
      float rd0 = rdeg[r0], rd1 = rdeg[r1];
      size_t o0 = (size_t)(m0 + r0) * 256 + nb * 128 + col;
      size_t o1 = (size_t)(m0 + r1) * 256 + nb * 128 + col;
      *(uint32_t*)&g_AggH[o0] = pack2h(accC[nf][0] * rd0, accC[nf][1] * rd0);
      *(uint32_t*)&g_AggH[o1] = pack2h(accC[nf][2] * rd1, accC[nf][3] * rd1);
    }
  }
}

// ===== gates: 32-col slice, 3 CTA/SM, 3-stage pipeline, fp16 exchange =====
// grid (4, NNODE/64): nh-major so 4 CTAs sharing an A block are co-resident.
#define GA 0                        // 3 x 8KB A stages
#define GB 24576                    // 3 x 12KB B stages
#define G_BIAS (24576 + 36864)      // 61440
#define SM_GATES (61440 + 2048)     // 63488

__global__ void __launch_bounds__(256, 3) k_gates() {
  extern __shared__ __align__(1024) char smem[];
  const uint32_t sb = smem_to_u32(smem);
  float* sbias = (float*)(smem + G_BIAS);
  const int tid = threadIdx.x;
  const int lid = tid & 31, wid = tid >> 5;
  const int nh = blockIdx.x;            // 0..3
  const int m0 = blockIdx.y * 64;
  const int cs = nh * 32;               // global gate-col base
  const int gate = wid >> 1;
  const int wm0g = (wid & 1) * 32;

  auto issueA = [&](int ch) {
    uint32_t base = sb + GA + (ch % 3) * 8192;
    const h16* src0;
    int ld, kk;
    if (ch < 4) { src0 = g_AggH; ld = 256; kk = ch * 64; }
    else { src0 = g_featH; ld = 128; kk = (ch - 4) * 64; }
#pragma unroll
    for (int i = 0; i < 2; i++) {
      int u = tid + 256 * i;
      int r = u >> 3, seg = u & 7;
      cp16(base + SWZ(r * 128 + seg * 16),
           src0 + (size_t)(m0 + r) * ld + kk + seg * 8);
    }
  };
  auto issueB = [&](int ch) {
    uint32_t base = sb + GB + (ch % 3) * 12288;
#pragma unroll
    for (int slot = 0; slot < 3; slot++) {
      int bg = (slot < 2) ? slot : (ch >= 4 ? 3 : 2);
      int r = tid >> 3, seg = tid & 7;   // 256 lines = 32 rows x 8 segs
      cp16(base + slot * 4096 + SWZ(r * 128 + seg * 16),
           g_Wg + (size_t)(bg * 128 + cs + r) * 384 + ch * 64 + seg * 8);
    }
  };
  issueA(0); issueB(0); CP_COMMIT();
  issueA(1); issueB(1); CP_COMMIT();
  for (int i = tid; i < 512; i += 256) sbias[i] = g_biasG[i];

  float acc[2][4][4];
#pragma unroll
  for (int mi = 0; mi < 2; mi++)
#pragma unroll
    for (int ni = 0; ni < 4; ni++)
#pragma unroll
      for (int q = 0; q < 4; q++) acc[mi][ni][q] = 0.f;

  const int j = lid >> 3, rr = lid & 7;
  for (int ch = 0; ch < 6; ch++) {
    if (ch < 5) CP_WAIT(1); else CP_WAIT(0);
    __syncthreads();
    if (ch + 2 < 6) { issueA(ch + 2); issueB(ch + 2); CP_COMMIT(); }
    bool active = (gate == 2) ? (ch < 4) : (gate == 3) ? (ch >= 4) : true;
    if (active) {
      const uint32_t abase = sb + GA + (ch % 3) * 8192;
      const uint32_t bbase =
          sb + GB + (ch % 3) * 12288 + ((gate < 2) ? gate : 2) * 4096;
#pragma unroll
      for (int kk = 0; kk < 4; kk++) {
        uint32_t ah[2][4], bh[4][2];
#pragma unroll
        for (int mi = 0; mi < 2; mi++) {
          int row = wm0g + mi * 16 + (j & 1) * 8 + rr;
          int kb = kk * 32 + (j >> 1) * 16;
          ldsm_x4(abase + SWZ(row * 128 + kb), ah[mi]);
        }
        {
          int n = (j >> 1) * 8 + rr;     // p = 0..1 -> 32 cols
          int kb = kk * 32 + (j & 1) * 16;
          uint32_t t[4];
          ldsm_x4(bbase + SWZ(n * 128 + kb), t);
          bh[0][0] = t[0]; bh[0][1] = t[1];
          bh[1][0] = t[2]; bh[1][1] = t[3];
          ldsm_x4(bbase + SWZ((n + 16) * 128 + kb), t);
          bh[2][0] = t[0]; bh[2][1] = t[1];
          bh[3][0] = t[2]; bh[3][1] = t[3];
        }
#pragma unroll
        for (int mi = 0; mi < 2; mi++)
#pragma unroll
          for (int ni = 0; ni < 4; ni++)
            mma16816(acc[mi][ni], ah[mi], bh[ni]);
      }
    }
  }
  __syncthreads();

  // ---- fp16 exchange in dead B region: 4 slabs x 64 rows x stride 34 ----
  // r,z pre-activated (sigmoid); i,h stored with bias added.
  h16* sG = (h16*)(smem + GB);
  const int gp = lid >> 2, tg = lid & 3;
#pragma unroll
  for (int mi = 0; mi < 2; mi++)
#pragma unroll
    for (int ni = 0; ni < 4; ni++) {
      int r = wm0g + mi * 16 + gp;
      int c = ni * 8 + tg * 2;
      int colg = cs + c;
      float v[4] = {acc[mi][ni][0], acc[mi][ni][1],
                    acc[mi][ni][2], acc[mi][ni][3]};
      if (gate == 0) {
        v[0] = sigf(v[0] + sbias[colg]); v[1] = sigf(v[1] + sbias[colg + 1]);
        v[2] = sigf(v[2] + sbias[colg]); v[3] = sigf(v[3] + sbias[colg + 1]);
      } else if (gate == 1) {
        v[0] = sigf(v[0] + sbias[128 + colg]); v[1] = sigf(v[1] + sbias[129 + colg]);
        v[2] = sigf(v[2] + sbias[128 + colg]); v[3] = sigf(v[3] + sbias[129 + colg]);
      } else if (gate == 2) {
        v[0] += sbias[256 + colg]; v[1] += sbias[257 + colg];
        v[2] += sbias[256 + colg]; v[3] += sbias[257 + colg];
      } else {
        v[0] += sbias[384 + colg]; v[1] += sbias[385 + colg];
        v[2] += sbias[384 + colg]; v[3] += sbias[385 + colg];
      }
      *(uint32_t*)&sG[(gate * 64 + r) * 34 + c] = pack2h(v[0], v[1]);
      *(uint32_t*)&sG[(gate * 64 + r + 8) * 34 + c] = pack2h(v[2], v[3]);
    }
  __syncthreads();

  // ---- GRU elementwise: 64 rows x 32 cols -> 8 cols per thread ----
  {
    const int row = tid >> 2, q = tid & 3;
    const int grow = m0 + row;
    const bool lastrow = (grow & 31) == 31;
    const int fstage = (4 + (nh >> 1)) % 3;   // chunk 4 -> stage 1, 5 -> stage 2
    const int fcb = (nh & 1) * 32;            // col base within feat chunk
    __align__(16) h16 oh[8];
#pragma unroll
    for (int c2 = 0; c2 < 4; c2++) {
      int lc = q * 8 + c2 * 2;
      uint32_t fh = *(uint32_t*)(smem + GA + fstage * 8192 +
                                 SWZ(row * 128 + (fcb + lc) * 2));
      float2 fvp = __half22float2(*(__half2*)&fh);
#pragma unroll
      for (int c1 = 0; c1 < 2; c1++) {
        int lcc = lc + c1;
        float r_ = h2f(sG[row * 34 + lcc]);
        float z_ = h2f(sG[(64 + row) * 34 + lcc]);
        float is = h2f(sG[(128 + row) * 34 + lcc]);
        float hs = h2f(sG[(192 + row) * 34 + lcc]);
        float ng = tanh_fast(is + r_ * hs);
        float f = (c1 == 0) ? fvp.x : fvp.y;
        float hn = (1.f - z_) * ng + z_ * f;
        oh[c2 * 2 + c1] = __float2half_rn(hn);
        if (lastrow) g_HNlast[(size_t)(grow >> 5) * 128 + cs + lcc] = hn;
      }
    }
    *(int4*)&g_HNh[(size_t)grow * 128 + cs + q * 8] = *(int4*)oh;
  }
}

// ========= U GEMM + FV + attention + readout (2 CTA/SM, fv fused) =========
#define SG 32768
#define A_MISC (2 * SG)
#define A_WV (2 * SG + 6656)
#define SM_ALPHA (A_WV + 32768)

__global__ void __launch_bounds__(256, 2) k_alpha(const float* __restrict__ cnt,
                                                  const float* __restrict__ we,
                                                  const float* __restrict__ b_v,
                                                  float* __restrict__ out) {
  extern __shared__ __align__(1024) char smem[];
  const uint32_t sb = smem_to_u32(smem);
  const int tid = threadIdx.x;
  const int lid = tid & 31, wid = tid >> 5;
  const int m0 = blockIdx.x * 128;
  const int g0 = m0 >> 5;
  const int wm0 = (wid & 3) * 32, wn0 = (wid >> 2) * 64;

  float* sFV = (float*)(smem + A_MISC);
  float* swe = sFV + 512;
  float* scnt = swe + 128;
  float* sPart = scnt + 128;
  float* sAl = sPart + 256;
  float* sLast = sAl + 128;

  auto issue = [&](int kc, int s) {
    uint32_t base = sb + s * SG;
#pragma unroll
    for (int i = 0; i < 4; i++) {
      int u = tid + 256 * i;
      int r = u >> 3, seg = u & 7;
      uint32_t d = SWZ(r * 128 + seg * 16);
      cp16(base + d, g_HNh + (size_t)(m0 + r) * 128 + kc + seg * 8);
      cp16(base + 16384 + d, g_Wu + (size_t)r * 128 + kc + seg * 8);
    }
  };

  issue(0, 0);
#pragma unroll
  for (int i = 0; i < 8; i++) {
    int u = tid + 256 * i;
    cp16(sb + A_WV + u * 16, g_Wv + u * 8);
  }
  CP_COMMIT();
  issue(64, 1);
  CP_COMMIT();

  if (tid < 128) { swe[tid] = we[tid]; scnt[tid] = cnt[m0 + tid]; }
#pragma unroll
  for (int i = 0; i < 2; i++) {
    int e = tid + 256 * i;
    sLast[e] = g_HNlast[(size_t)g0 * 128 + e];
  }

  float acc[2][8][4];
#pragma unroll
  for (int mi = 0; mi < 2; mi++)
#pragma unroll
    for (int ni = 0; ni < 8; ni++)
#pragma unroll
      for (int q = 0; q < 4; q++) acc[mi][ni][q] = 0.f;

  const int j = lid >> 3, rr = lid & 7;
#pragma unroll
  for (int c = 0; c < 2; c++) {
    if (c == 0) CP_WAIT(1); else CP_WAIT(0);
    __syncthreads();
    const uint32_t st = sb + c * SG;
#pragma unroll
    for (int kk = 0; kk < 4; kk++) {
      uint32_t ah[2][4], bh[8][2];
#pragma unroll
      for (int mi = 0; mi < 2; mi++) {
        int row = wm0 + mi * 16 + (j & 1) * 8 + rr;
        int kb = kk * 32 + (j >> 1) * 16;
        ldsm_x4(st + SWZ(row * 128 + kb), ah[mi]);
      }
#pragma unroll
      for (int p = 0; p < 4; p++) {
        int n = wn0 + p * 16 + (j >> 1) * 8 + rr;
        int kb = kk * 32 + (j & 1) * 16;
        uint32_t t[4];
        ldsm_x4(st + 16384 + SWZ(n * 128 + kb), t);
        bh[2 * p][0] = t[0]; bh[2 * p][1] = t[1];
        bh[2 * p + 1][0] = t[2]; bh[2 * p + 1][1] = t[3];
      }
#pragma unroll
      for (int mi = 0; mi < 2; mi++)
#pragma unroll
        for (int ni = 0; ni < 8; ni++)
          mma16816(acc[mi][ni], ah[mi], bh[ni]);
    }
  }
  __syncthreads();

  // FV = HNlast(f32) . Wv^T + b_v
#pragma unroll
  for (int e2 = 0; e2 < 2; e2++) {
    int e = tid + 256 * e2;
    int gl = e >> 7, jx = e & 127;
    const __half2* wv = (const __half2*)(smem + A_WV + jx * 256);
    const float* hl = sLast + gl * 128;
    float s = b_v[jx];
#pragma unroll 8
    for (int kk = 0; kk < 64; kk++) {
      int k2 = (kk + jx) & 63;
      float2 w = __half22float2(wv[k2]);
      s += hl[2 * k2] * w.x + hl[2 * k2 + 1] * w.y;
    }
    sFV[e] = s;
  }
  __syncthreads();

  const int gp = lid >> 2, tg = lid & 3;
#pragma unroll
  for (int mi = 0; mi < 2; mi++) {
    int base = wm0 + mi * 16;
    int gl = base >> 5;
    float p0 = 0.f, p1 = 0.f;
#pragma unroll
    for (int ni = 0; ni < 8; ni++) {
      int jx = wn0 + ni * 8 + tg * 2;
      float fv0 = sFV[gl * 128 + jx], fv1 = sFV[gl * 128 + jx + 1];
      float w0 = swe[jx], w1 = swe[jx + 1];
      p0 += w0 * sigf(acc[mi][ni][0] + fv0) + w1 * sigf(acc[mi][ni][1] + fv1);
      p1 += w0 * sigf(acc[mi][ni][2] + fv0) + w1 * sigf(acc[mi][ni][3] + fv1);
    }
    p0 += __shfl_xor_sync(0xffffffffu, p0, 1);
    p0 += __shfl_xor_sync(0xffffffffu, p0, 2);
    p1 += __shfl_xor_sync(0xffffffffu, p1, 1);
    p1 += __shfl_xor_sync(0xffffffffu, p1, 2);
    if (tg == 0) {
      sPart[(wid >> 2) * 128 + base + gp] = p0;
      sPart[(wid >> 2) * 128 + base + gp + 8] = p1;
    }
  }
  __syncthreads();
  if (tid < 128) sAl[tid] = (sPart[tid] + sPart[128 + tid]) * scnt[tid];
  __syncthreads();

  {
    int gl = tid >> 6, jp = tid & 63;
    int col0 = 2 * jp;
    int stg = col0 >> 6, cl = col0 & 63;
    float a0 = 0.f, a1 = 0.f;
#pragma unroll
    for (int n = 0; n < 32; n++) {
      uint32_t hv = *(uint32_t*)(smem + stg * SG +
                                 SWZ((gl * 32 + n) * 128 + cl * 2));
      float2 h = __half22float2(*(__half2*)&hv);
      float al = sAl[gl * 32 + n];
      a0 += h.x * al;
      a1 += h.y * al;
    }
    size_t ob = (size_t)(g0 + gl) * 256;
    *(float2*)&out[ob + col0] = make_float2(a0, a1);
    *(float2*)&out[ob + 128 + col0] =
        make_float2(sLast[gl * 128 + col0], sLast[gl * 128 + col0 + 1]);
  }
}

// ================= host =================
extern "C" void kernel_launch(void* const* d_in, const int* in_sizes, int n_in,
                              void* d_out, int out_size) {
  const float* feat = (const float*)d_in[0];
  const float* cnt  = (const float*)d_in[1];
  const float* W_in = (const float*)d_in[2];
  const float* b_in = (const float*)d_in[3];
  const float* W_og = (const float*)d_in[4];
  const float* b_og = (const float*)d_in[5];
  const float* W_ih = (const float*)d_in[6];
  const float* b_ih = (const float*)d_in[7];
  const float* W_hh = (const float*)d_in[8];
  const float* b_hh = (const float*)d_in[9];
  const float* W_u  = (const float*)d_in[10];
  const float* W_v  = (const float*)d_in[11];
  const float* b_v  = (const float*)d_in[12];
  const float* w_e  = (const float*)d_in[13];
  const int*   src  = (const int*)d_in[14];
  const int*   dst  = (const int*)d_in[15];
  float* out = (float*)d_out;

  static bool attr_done = false;
  if (!attr_done) {
    cudaFuncSetAttribute(k_yagg, cudaFuncAttributeMaxDynamicSharedMemorySize, SM_YAGG);
    cudaFuncSetAttribute(k_gates, cudaFuncAttributeMaxDynamicSharedMemorySize, SM_GATES);
    cudaFuncSetAttribute(k_alpha, cudaFuncAttributeMaxDynamicSharedMemorySize, SM_ALPHA);
    attr_done = true;
  }

  k_pack<<<2048, 256>>>(feat, W_in, W_og, W_ih, W_hh, W_u, W_v,
                        b_in, b_og, b_ih, b_hh);
  k_build_adj<<<NEDGE / 256, 256>>>(src, dst);

  k_yagg<<<dim3(NNODE / 128, 2), 256, SM_YAGG>>>();
  k_gates<<<dim3(4, NNODE / 64), 256, SM_GATES>>>();
  k_alpha<<<NNODE / 128, 256, SM_ALPHA>>>(cnt, w_e, b_v, out);
}

// round 16
// speedup vs baseline: 1.3521x; 1.0698x over previous
#include <cuda_runtime.h>
#include <cuda_fp16.h>
#include <cstdint>

#define NGRAPH 8192
#define NNODE (NGRAPH * 32)
#define NEDGE 524288

typedef __half h16;

// ================= static device scratch =================
__device__ __align__(16) h16  g_adjh[NGRAPH * 1024];   // fp16 counts
__device__ __align__(16) h16  g_featH[(size_t)NNODE * 128];
__device__ __align__(16) h16  g_AggH[(size_t)NNODE * 256];
__device__ __align__(16) h16  g_HNh[(size_t)NNODE * 128];
__device__ __align__(16) float g_HNlast[(size_t)NGRAPH * 128];
__device__ __align__(16) h16  g_Wio[256 * 128];
__device__ __align__(16) h16  g_Wg[512 * 384];
__device__ __align__(16) h16  g_Wu[128 * 128];
__device__ __align__(16) h16  g_Wv[128 * 128];
__device__ __align__(16) float g_biasY[256];
__device__ __align__(16) float g_biasG[512];

// ================= helpers =================
__device__ __forceinline__ uint32_t smem_to_u32(const void* p) {
  uint32_t a;
  asm("{ .reg .u64 tmp; cvta.to.shared.u64 tmp, %1; cvt.u32.u64 %0, tmp; }"
      : "=r"(a) : "l"(p));
  return a;
}
#define SWZ(off) ((off) ^ (((off) >> 3) & 0x70))

__device__ __forceinline__ void cp16(uint32_t dst, const void* src) {
  asm volatile("cp.async.cg.shared.global [%0], [%1], 16;" ::"r"(dst), "l"(src));
}
#define CP_COMMIT() asm volatile("cp.async.commit_group;" ::: "memory")
#define CP_WAIT(n) asm volatile("cp.async.wait_group %0;" ::"n"(n) : "memory")

__device__ __forceinline__ void ldsm_x4(uint32_t addr, uint32_t* r) {
  asm volatile("ldmatrix.sync.aligned.m8n8.x4.shared.b16 {%0,%1,%2,%3}, [%4];"
               : "=r"(r[0]), "=r"(r[1]), "=r"(r[2]), "=r"(r[3]) : "r"(addr));
}
__device__ __forceinline__ void ldsm_x4_t(uint32_t addr, uint32_t* r) {
  asm volatile("ldmatrix.sync.aligned.m8n8.x4.trans.shared.b16 {%0,%1,%2,%3}, [%4];"
               : "=r"(r[0]), "=r"(r[1]), "=r"(r[2]), "=r"(r[3]) : "r"(addr));
}
__device__ __forceinline__ void mma16816(float* d, const uint32_t* a,
                                         const uint32_t* b) {
  asm volatile(
      "mma.sync.aligned.m16n8k16.row.col.f32.f16.f16.f32 "
      "{%0,%1,%2,%3}, {%4,%5,%6,%7}, {%8,%9}, {%0,%1,%2,%3};"
      : "+f"(d[0]), "+f"(d[1]), "+f"(d[2]), "+f"(d[3])
      : "r"(a[0]), "r"(a[1]), "r"(a[2]), "r"(a[3]), "r"(b[0]), "r"(b[1]));
}

__device__ __forceinline__ float sigf(float x) { return 1.f / (1.f + __expf(-x)); }
__device__ __forceinline__ float tanh_fast(float x) {
  float e2x = __expf(2.f * x);
  return 1.f - 2.f / (e2x + 1.f);
}
__device__ __forceinline__ float h2f(h16 v) { return __half2float(v); }
__device__ __forceinline__ uint32_t pack2h(float a, float b) {
  __half2 h = __floats2half2_rn(a, b);
  return *(uint32_t*)&h;
}

// ================= adjacency build (zeroing merged into k_pack) ==========
__global__ void k_build_adj(const int* __restrict__ src, const int* __restrict__ dst) {
  int e = blockIdx.x * blockDim.x + threadIdx.x;
  if (e >= NEDGE) return;
  int d = dst[e];
  int s = src[e];
  int idx = ((d >> 5) << 10) + ((d & 31) << 5) + (s & 31);
  __half2 v = (idx & 1) ? __floats2half2_rn(0.f, 1.f)
                        : __floats2half2_rn(1.f, 0.f);
  atomicAdd(&((__half2*)g_adjh)[idx >> 1], v);
}

// ================= weight pack + feat convert + adj zero =================
__global__ void k_pack(const float* __restrict__ feat,
                       const float* __restrict__ W_in, const float* __restrict__ W_og,
                       const float* __restrict__ W_ih, const float* __restrict__ W_hh,
                       const float* __restrict__ W_u, const float* __restrict__ W_v,
                       const float* __restrict__ b_in, const float* __restrict__ b_og,
                       const float* __restrict__ b_ih, const float* __restrict__ b_hh) {
  int i0 = blockIdx.x * 256 + threadIdx.x;
  int stride = gridDim.x * 256;
  {
    int4* p = (int4*)g_adjh;
    const int n4 = NGRAPH * 1024 * 2 / 16;
    int4 z = make_int4(0, 0, 0, 0);
    for (int i = i0; i < n4; i += stride) p[i] = z;
  }
  {
    const float4* f4 = (const float4*)feat;
    const size_t n4 = (size_t)NNODE * 32;
    for (size_t i = i0; i < n4; i += stride) {
      float4 v = f4[i];
      __half2* dstp = (__half2*)&g_featH[i * 4];
      dstp[0] = __floats2half2_rn(v.x, v.y);
      dstp[1] = __floats2half2_rn(v.z, v.w);
    }
  }
  for (int i = i0; i < 256 * 128; i += stride) {
    int r = i >> 7, c = i & 127;
    float v = (r < 128) ? W_in[r * 128 + c] : W_og[(r - 128) * 128 + c];
    g_Wio[i] = __float2half_rn(v);
  }
  for (int i = i0; i < 512 * 384; i += stride) {
    int r = i / 384, c = i % 384;
    int blk = r >> 7, rr = r & 127;
    float v;
    if (blk == 0)      v = (c < 256) ? W_ih[rr * 256 + c] : W_hh[rr * 128 + (c - 256)];
    else if (blk == 1) v = (c < 256) ? W_ih[(128 + rr) * 256 + c] : W_hh[(128 + rr) * 128 + (c - 256)];
    else if (blk == 2) v = (c < 256) ? W_ih[(256 + rr) * 256 + c] : 0.f;
    else               v = (c < 256) ? 0.f : W_hh[(256 + rr) * 128 + (c - 256)];
    g_Wg[i] = __float2half_rn(v);
  }
  for (int i = i0; i < 128 * 128; i += stride) {
    g_Wu[i] = __float2half_rn(W_u[i]);
    g_Wv[i] = __float2half_rn(W_v[i]);
  }
  for (int i = i0; i < 256; i += stride)
    g_biasY[i] = (i < 128) ? b_in[i] : b_og[i - 128];
  for (int i = i0; i < 512; i += stride) {
    float v;
    if (i < 256)      v = b_ih[i] + b_hh[i];
    else if (i < 384) v = b_ih[i];
    else              v = b_hh[i - 128];
    g_biasG[i] = v;
  }
}

// ================= Y GEMM + tensorized aggregation (2 CTA/SM) ====
#define YSG 32768
#define Y_ADJ 65536
#define Y_RDEG (65536 + 10240)
#define SM_YAGG (65536 + 10240 + 512)

__global__ void __launch_bounds__(256, 2) k_yagg() {
  extern __shared__ __align__(1024) char smem[];
  const uint32_t sb = smem_to_u32(smem);
  const int tid = threadIdx.x;
  const int lid = tid & 31, wid = tid >> 5;
  const int m0 = blockIdx.x * 128;
  const int nb = blockIdx.y;
  const int g0 = m0 >> 5;
  const int wm0 = (wid & 3) * 32, wn0 = (wid >> 2) * 64;

  const h16* Bh = g_Wio + (size_t)nb * 128 * 128;
  float* rdeg = (float*)(smem + Y_RDEG);

  auto issue = [&](int kc, int s) {
    uint32_t base = sb + s * YSG;
#pragma unroll
    for (int i = 0; i < 4; i++) {
      int u = tid + 256 * i;
      int r = u >> 3, seg = u & 7;
      uint32_t d = SWZ(r * 128 + seg * 16);
      cp16(base + d, g_featH + (size_t)(m0 + r) * 128 + kc + seg * 8);
      cp16(base + 16384 + d, Bh + (size_t)r * 128 + kc + seg * 8);
    }
    CP_COMMIT();
  };

  issue(0, 0);
  issue(64, 1);

  const h16* adjg = g_adjh + ((size_t)g0 << 10);
#pragma unroll
  for (int i = 0; i < 16; i++) {
    int u = tid + 256 * i;
    int gl = u >> 10, rem = u & 1023;
    int n = rem >> 5, k = rem & 31;
    int row, col;
    if (nb == 0) { row = gl * 32 + n; col = k; }
    else { row = gl * 32 + k; col = n; }
    *(h16*)(smem + Y_ADJ + row * 80 + col * 2) = adjg[u];
  }
  __syncthreads();
  if (tid < 128) {
    float s = 0.f;
#pragma unroll
    for (int k = 0; k < 32; k++)
      s += h2f(*(h16*)(smem + Y_ADJ + tid * 80 + k * 2));
    rdeg[tid] = 1.f / fmaxf(s, 1.f);
  }

  float acc[2][8][4];
#pragma unroll
  for (int mi = 0; mi < 2; mi++)
#pragma unroll
    for (int ni = 0; ni < 8; ni++)
#pragma unroll
      for (int q = 0; q < 4; q++) acc[mi][ni][q] = 0.f;

  const int j = lid >> 3, rr = lid & 7;
#pragma unroll
  for (int c = 0; c < 2; c++) {
    if (c == 0) CP_WAIT(1); else CP_WAIT(0);
    __syncthreads();
    const uint32_t st = sb + c * YSG;
#pragma unroll
    for (int kk = 0; kk < 4; kk++) {
      uint32_t ah[2][4], bh[8][2];
#pragma unroll
      for (int mi = 0; mi < 2; mi++) {
        int row = wm0 + mi * 16 + (j & 1) * 8 + rr;
        int kb = kk * 32 + (j >> 1) * 16;
        ldsm_x4(st + SWZ(row * 128 + kb), ah[mi]);
      }
#pragma unroll
      for (int p = 0; p < 4; p++) {
        int n = wn0 + p * 16 + (j >> 1) * 8 + rr;
        int kb = kk * 32 + (j & 1) * 16;
        uint32_t t[4];
        ldsm_x4(st + 16384 + SWZ(n * 128 + kb), t);
        bh[2 * p][0] = t[0]; bh[2 * p][1] = t[1];
        bh[2 * p + 1][0] = t[2]; bh[2 * p + 1][1] = t[3];
      }
#pragma unroll
      for (int mi = 0; mi < 2; mi++)
#pragma unroll
        for (int ni = 0; ni < 8; ni++)
          mma16816(acc[mi][ni], ah[mi], bh[ni]);
    }
  }
  __syncthreads();

  const int gp = lid >> 2, tg = lid & 3;
#pragma unroll
  for (int mi = 0; mi < 2; mi++)
#pragma unroll
    for (int ni = 0; ni < 8; ni++) {
      int r = wm0 + mi * 16 + gp;
      int c = wn0 + ni * 8 + tg * 2;
      float b0 = g_biasY[nb * 128 + c], b1 = g_biasY[nb * 128 + c + 1];
      uint32_t tileo = (c >> 6) * 16384;
      *(uint32_t*)(smem + tileo + SWZ(r * 128 + (c & 63) * 2)) =
          pack2h(acc[mi][ni][0] + b0, acc[mi][ni][1] + b1);
      *(uint32_t*)(smem + tileo + SWZ((r + 8) * 128 + (c & 63) * 2)) =
          pack2h(acc[mi][ni][2] + b0, acc[mi][ni][3] + b1);
    }
  __syncthreads();

  {
    const int arow = wid * 16;
    const int krow0 = (wid >> 1) * 32;
    uint32_t af[2][4];
#pragma unroll
    for (int ks = 0; ks < 2; ks++) {
      uint32_t addr = sb + Y_ADJ + (arow + (j & 1) * 8 + rr) * 80 +
                      (j >> 1) * 16 + ks * 32;
      ldsm_x4(addr, af[ks]);
    }
    float accC[16][4];
#pragma unroll
    for (int nf = 0; nf < 16; nf++)
#pragma unroll
      for (int q = 0; q < 4; q++) accC[nf][q] = 0.f;
#pragma unroll
    for (int p = 0; p < 8; p++) {
#pragma unroll
      for (int ks = 0; ks < 2; ks++) {
        int krow = krow0 + ks * 16 + (j & 1) * 8 + rr;
        int c = p * 16 + (j >> 1) * 8;
        uint32_t t[4];
        ldsm_x4_t(sb + (c >> 6) * 16384 + SWZ(krow * 128 + (c & 63) * 2), t);
        mma16816(accC[2 * p], af[ks], t);
        mma16816(accC[2 * p + 1], af[ks], t + 2);
      }
    }
#pragma unroll
    for (int nf = 0; nf < 16; nf++) {
      int col = nf * 8 + tg * 2;
      int r0 = arow + gp, r1 = arow + gp + 8;
      float rd0 = rdeg[r0], rd1 = rdeg[r1];
      size_t o0 = (size_t)(m0 + r0) * 256 + nb * 128 + col;
      size_t o1 = (size_t)(m0 + r1) * 256 + nb * 128 + col;
      *(uint32_t*)&g_AggH[o0] = pack2h(accC[nf][0] * rd0, accC[nf][1] * rd0);
      *(uint32_t*)&g_AggH[o1] = pack2h(accC[nf][2] * rd1, accC[nf][3] * rd1);
    }
  }
}

// ===== gates: 32-col slice, 3 CTA/SM, unrolled pipeline, hoisted addrs ====
#define GA 0                        // 3 x 8KB A stages
#define GB 24576                    // 3 x 12KB B stages
#define G_BIAS (24576 + 36864)      // 61440
#define SM_GATES (61440 + 2048)     // 63488

__global__ void __launch_bounds__(256, 3) k_gates() {
  extern __shared__ __align__(1024) char smem[];
  const uint32_t sb = smem_to_u32(smem);
  float* sbias = (float*)(smem + G_BIAS);
  const int tid = threadIdx.x;
  const int lid = tid & 31, wid = tid >> 5;
  const int nh = blockIdx.x;            // 0..3
  const int m0 = blockIdx.y * 64;
  const int cs = nh * 32;               // global gate-col base
  const int gate = wid >> 1;
  const int wm0g = (wid & 1) * 32;

  // ---- hoisted per-thread issue addressing ----
  const int rA0 = tid >> 3, segA = tid & 7;
  const int rA1 = (tid + 256) >> 3;
  const uint32_t dA0 = SWZ(rA0 * 128 + segA * 16);
  const uint32_t dA1 = SWZ(rA1 * 128 + segA * 16);
  const h16* aggS0 = g_AggH + (size_t)(m0 + rA0) * 256 + segA * 8;
  const h16* aggS1 = g_AggH + (size_t)(m0 + rA1) * 256 + segA * 8;
  const h16* featS0 = g_featH + (size_t)(m0 + rA0) * 128 + segA * 8;
  const h16* featS1 = g_featH + (size_t)(m0 + rA1) * 128 + segA * 8;
  const h16* wgBase = g_Wg + (size_t)(cs + rA0) * 384 + segA * 8;
  // bg strides: bg*128 rows * 384
  const uint32_t dB = dA0;

  auto issue = [&](int ch) {   // ch is compile-time under full unroll
    uint32_t baseA = sb + GA + (ch % 3) * 8192;
    if (ch < 4) {
      cp16(baseA + dA0, aggS0 + ch * 64);
      cp16(baseA + dA1, aggS1 + ch * 64);
    } else {
      cp16(baseA + dA0, featS0 + (ch - 4) * 64);
      cp16(baseA + dA1, featS1 + (ch - 4) * 64);
    }
    uint32_t baseB = sb + GB + (ch % 3) * 12288;
    cp16(baseB + dB, wgBase + ch * 64);
    cp16(baseB + 4096 + dB, wgBase + 128 * 384 + ch * 64);
    cp16(baseB + 8192 + dB,
         wgBase + (ch >= 4 ? 3 : 2) * 128 * 384 + ch * 64);
    CP_COMMIT();
  };
  issue(0);
  issue(1);
  for (int i = tid; i < 512; i += 256) sbias[i] = g_biasG[i];

  float acc[2][4][4];
#pragma unroll
  for (int mi = 0; mi < 2; mi++)
#pragma unroll
    for (int ni = 0; ni < 4; ni++)
#pragma unroll
      for (int q = 0; q < 4; q++) acc[mi][ni][q] = 0.f;

  // ---- hoisted ldsm offsets (within a stage) ----
  const int j = lid >> 3, rr = lid & 7;
  const uint32_t aO = SWZ((wm0g + (j & 1) * 8 + rr) * 128 + (j >> 1) * 16);
  const uint32_t aO1 = SWZ((wm0g + 16 + (j & 1) * 8 + rr) * 128 + (j >> 1) * 16);
  const uint32_t bO = SWZ(((j >> 1) * 8 + rr) * 128 + (j & 1) * 16);
  const uint32_t bO1 = SWZ((16 + (j >> 1) * 8 + rr) * 128 + (j & 1) * 16);
  const uint32_t bslotoff = ((gate < 2) ? gate : 2) * 4096;

#pragma unroll
  for (int ch = 0; ch < 6; ch++) {
    if (ch < 5) CP_WAIT(1); else CP_WAIT(0);
    __syncthreads();
    if (ch + 2 < 6) issue(ch + 2);
    bool active = (gate == 2) ? (ch < 4) : (gate == 3) ? (ch >= 4) : true;
    if (active) {
      const uint32_t abase = sb + GA + (ch % 3) * 8192;
      const uint32_t bbase = sb + GB + (ch % 3) * 12288 + bslotoff;
#pragma unroll
      for (int kk = 0; kk < 4; kk++) {
        const uint32_t ko = kk * 32;  // SWZ-invariant (bits [5:0] only? no —
        // kk*32 touches bit5..6; bit6 participates in SWZ. Use full SWZ:
        uint32_t ah[2][4], bh[4][2];
        ldsm_x4(abase + (aO ^ SWZ(ko)) , ah[0]);
        ldsm_x4(abase + (aO1 ^ SWZ(ko)), ah[1]);
        {
          uint32_t t[4];
          ldsm_x4(bbase + (bO ^ SWZ(ko)), t);
          bh[0][0] = t[0]; bh[0][1] = t[1];
          bh[1][0] = t[2]; bh[1][1] = t[3];
          ldsm_x4(bbase + (bO1 ^ SWZ(ko)), t);
          bh[2][0] = t[0]; bh[2][1] = t[1];
          bh[3][0] = t[2]; bh[3][1] = t[3];
        }
#pragma unroll
        for (int mi = 0; mi < 2; mi++)
#pragma unroll
          for (int ni = 0; ni < 4; ni++)
            mma16816(acc[mi][ni], ah[mi], bh[ni]);
      }
    }
  }
  __syncthreads();

  // ---- fp16 exchange in dead B region: 4 slabs x 64 rows x stride 34 ----
  h16* sG = (h16*)(smem + GB);
  const int gp = lid >> 2, tg = lid & 3;
#pragma unroll
  for (int mi = 0; mi < 2; mi++)
#pragma unroll
    for (int ni = 0; ni < 4; ni++) {
      int r = wm0g + mi * 16 + gp;
      int c = ni * 8 + tg * 2;
      int colg = cs + c;
      float v[4] = {acc[mi][ni][0], acc[mi][ni][1],
                    acc[mi][ni][2], acc[mi][ni][3]};
      if (gate == 0) {
        v[0] = sigf(v[0] + sbias[colg]); v[1] = sigf(v[1] + sbias[colg + 1]);
        v[2] = sigf(v[2] + sbias[colg]); v[3] = sigf(v[3] + sbias[colg + 1]);
      } else if (gate == 1) {
        v[0] = sigf(v[0] + sbias[128 + colg]); v[1] = sigf(v[1] + sbias[129 + colg]);
        v[2] = sigf(v[2] + sbias[128 + colg]); v[3] = sigf(v[3] + sbias[129 + colg]);
      } else if (gate == 2) {
        v[0] += sbias[256 + colg]; v[1] += sbias[257 + colg];
        v[2] += sbias[256 + colg]; v[3] += sbias[257 + colg];
      } else {
        v[0] += sbias[384 + colg]; v[1] += sbias[385 + colg];
        v[2] += sbias[384 + colg]; v[3] += sbias[385 + colg];
      }
      *(uint32_t*)&sG[(gate * 64 + r) * 34 + c] = pack2h(v[0], v[1]);
      *(uint32_t*)&sG[(gate * 64 + r + 8) * 34 + c] = pack2h(v[2], v[3]);
    }
  __syncthreads();

  // ---- GRU elementwise: 64 rows x 32 cols -> 8 cols per thread ----
  {
    const int row = tid >> 2, q = tid & 3;
    const int grow = m0 + row;
    const bool lastrow = (grow & 31) == 31;
    const int fstage = (4 + (nh >> 1)) % 3;
    const int fcb = (nh & 1) * 32;
    __align__(16) h16 oh[8];
#pragma unroll
    for (int c2 = 0; c2 < 4; c2++) {
      int lc = q * 8 + c2 * 2;
      uint32_t fh = *(uint32_t*)(smem + GA + fstage * 8192 +
                                 SWZ(row * 128 + (fcb + lc) * 2));
      float2 fvp = __half22float2(*(__half2*)&fh);
#pragma unroll
      for (int c1 = 0; c1 < 2; c1++) {
        int lcc = lc + c1;
        float r_ = h2f(sG[row * 34 + lcc]);
        float z_ = h2f(sG[(64 + row) * 34 + lcc]);
        float is = h2f(sG[(128 + row) * 34 + lcc]);
        float hs = h2f(sG[(192 + row) * 34 + lcc]);
        float ng = tanh_fast(is + r_ * hs);
        float f = (c1 == 0) ? fvp.x : fvp.y;
        float hn = (1.f - z_) * ng + z_ * f;
        oh[c2 * 2 + c1] = __float2half_rn(hn);
        if (lastrow) g_HNlast[(size_t)(grow >> 5) * 128 + cs + lcc] = hn;
      }
    }
    *(int4*)&g_HNh[(size_t)grow * 128 + cs + q * 8] = *(int4*)oh;
  }
}

// ========= U GEMM + FV + attention + readout (2 CTA/SM, fv fused) =========
#define SG 32768
#define A_MISC (2 * SG)
#define A_WV (2 * SG + 6656)
#define SM_ALPHA (A_WV + 32768)

__global__ void __launch_bounds__(256, 2) k_alpha(const float* __restrict__ cnt,
                                                  const float* __restrict__ we,
                                                  const float* __restrict__ b_v,
                                                  float* __restrict__ out) {
  extern __shared__ __align__(1024) char smem[];
  const uint32_t sb = smem_to_u32(smem);
  const int tid = threadIdx.x;
  const int lid = tid & 31, wid = tid >> 5;
  const int m0 = blockIdx.x * 128;
  const int g0 = m0 >> 5;
  const int wm0 = (wid & 3) * 32, wn0 = (wid >> 2) * 64;

  float* sFV = (float*)(smem + A_MISC);
  float* swe = sFV + 512;
  float* scnt = swe + 128;
  float* sPart = scnt + 128;
  float* sAl = sPart + 256;
  float* sLast = sAl + 128;

  auto issue = [&](int kc, int s) {
    uint32_t base = sb + s * SG;
#pragma unroll
    for (int i = 0; i < 4; i++) {
      int u = tid + 256 * i;
      int r = u >> 3, seg = u & 7;
      uint32_t d = SWZ(r * 128 + seg * 16);
      cp16(base + d, g_HNh + (size_t)(m0 + r) * 128 + kc + seg * 8);
      cp16(base + 16384 + d, g_Wu + (size_t)r * 128 + kc + seg * 8);
    }
  };

  issue(0, 0);
#pragma unroll
  for (int i = 0; i < 8; i++) {
    int u = tid + 256 * i;
    cp16(sb + A_WV + u * 16, g_Wv + u * 8);
  }
  CP_COMMIT();
  issue(64, 1);
  CP_COMMIT();

  if (tid < 128) { swe[tid] = we[tid]; scnt[tid] = cnt[m0 + tid]; }
#pragma unroll
  for (int i = 0; i < 2; i++) {
    int e = tid + 256 * i;
    sLast[e] = g_HNlast[(size_t)g0 * 128 + e];
  }

  float acc[2][8][4];
#pragma unroll
  for (int mi = 0; mi < 2; mi++)
#pragma unroll
    for (int ni = 0; ni < 8; ni++)
#pragma unroll
      for (int q = 0; q < 4; q++) acc[mi][ni][q] = 0.f;

  const int j = lid >> 3, rr = lid & 7;
#pragma unroll
  for (int c = 0; c < 2; c++) {
    if (c == 0) CP_WAIT(1); else CP_WAIT(0);
    __syncthreads();
    const uint32_t st = sb + c * SG;
#pragma unroll
    for (int kk = 0; kk < 4; kk++) {
      uint32_t ah[2][4], bh[8][2];
#pragma unroll
      for (int mi = 0; mi < 2; mi++) {
        int row = wm0 + mi * 16 + (j & 1) * 8 + rr;
        int kb = kk * 32 + (j >> 1) * 16;
        ldsm_x4(st + SWZ(row * 128 + kb), ah[mi]);
      }
#pragma unroll
      for (int p = 0; p < 4; p++) {
        int n = wn0 + p * 16 + (j >> 1) * 8 + rr;
        int kb = kk * 32 + (j & 1) * 16;
        uint32_t t[4];
        ldsm_x4(st + 16384 + SWZ(n * 128 + kb), t);
        bh[2 * p][0] = t[0]; bh[2 * p][1] = t[1];
        bh[2 * p + 1][0] = t[2]; bh[2 * p + 1][1] = t[3];
      }
#pragma unroll
      for (int mi = 0; mi < 2; mi++)
#pragma unroll
        for (int ni = 0; ni < 8; ni++)
          mma16816(acc[mi][ni], ah[mi], bh[ni]);
    }
  }
  __syncthreads();

  // FV = HNlast(f32) . Wv^T + b_v
#pragma unroll
  for (int e2 = 0; e2 < 2; e2++) {
    int e = tid + 256 * e2;
    int gl = e >> 7, jx = e & 127;
    const __half2* wv = (const __half2*)(smem + A_WV + jx * 256);
    const float* hl = sLast + gl * 128;
    float s = b_v[jx];
#pragma unroll 8
    for (int kk = 0; kk < 64; kk++) {
      int k2 = (kk + jx) & 63;
      float2 w = __half22float2(wv[k2]);
      s += hl[2 * k2] * w.x + hl[2 * k2 + 1] * w.y;
    }
    sFV[e] = s;
  }
  __syncthreads();

  const int gp = lid >> 2, tg = lid & 3;
#pragma unroll
  for (int mi = 0; mi < 2; mi++) {
    int base = wm0 + mi * 16;
    int gl = base >> 5;
    float p0 = 0.f, p1 = 0.f;
#pragma unroll
    for (int ni = 0; ni < 8; ni++) {
      int jx = wn0 + ni * 8 + tg * 2;
      float fv0 = sFV[gl * 128 + jx], fv1 = sFV[gl * 128 + jx + 1];
      float w0 = swe[jx], w1 = swe[jx + 1];
      p0 += w0 * sigf(acc[mi][ni][0] + fv0) + w1 * sigf(acc[mi][ni][1] + fv1);
      p1 += w0 * sigf(acc[mi][ni][2] + fv0) + w1 * sigf(acc[mi][ni][3] + fv1);
    }
    p0 += __shfl_xor_sync(0xffffffffu, p0, 1);
    p0 += __shfl_xor_sync(0xffffffffu, p0, 2);
    p1 += __shfl_xor_sync(0xffffffffu, p1, 1);
    p1 += __shfl_xor_sync(0xffffffffu, p1, 2);
    if (tg == 0) {
      sPart[(wid >> 2) * 128 + base + gp] = p0;
      sPart[(wid >> 2) * 128 + base + gp + 8] = p1;
    }
  }
  __syncthreads();
  if (tid < 128) sAl[tid] = (sPart[tid] + sPart[128 + tid]) * scnt[tid];
  __syncthreads();

  {
    int gl = tid >> 6, jp = tid & 63;
    int col0 = 2 * jp;
    int stg = col0 >> 6, cl = col0 & 63;
    float a0 = 0.f, a1 = 0.f;
#pragma unroll
    for (int n = 0; n < 32; n++) {
      uint32_t hv = *(uint32_t*)(smem + stg * SG +
                                 SWZ((gl * 32 + n) * 128 + cl * 2));
      float2 h = __half22float2(*(__half2*)&hv);
      float al = sAl[gl * 32 + n];
      a0 += h.x * al;
      a1 += h.y * al;
    }
    size_t ob = (size_t)(g0 + gl) * 256;
    *(float2*)&out[ob + col0] = make_float2(a0, a1);
    *(float2*)&out[ob + 128 + col0] =
        make_float2(sLast[gl * 128 + col0], sLast[gl * 128 + col0 + 1]);
  }
}

// ================= host =================
extern "C" void kernel_launch(void* const* d_in, const int* in_sizes, int n_in,
                              void* d_out, int out_size) {
  const float* feat = (const float*)d_in[0];
  const float* cnt  = (const float*)d_in[1];
  const float* W_in = (const float*)d_in[2];
  const float* b_in = (const float*)d_in[3];
  const float* W_og = (const float*)d_in[4];
  const float* b_og = (const float*)d_in[5];
  const float* W_ih = (const float*)d_in[6];
  const float* b_ih = (const float*)d_in[7];
  const float* W_hh = (const float*)d_in[8];
  const float* b_hh = (const float*)d_in[9];
  const float* W_u  = (const float*)d_in[10];
  const float* W_v  = (const float*)d_in[11];
  const float* b_v  = (const float*)d_in[12];
  const float* w_e  = (const float*)d_in[13];
  const int*   src  = (const int*)d_in[14];
  const int*   dst  = (const int*)d_in[15];
  float* out = (float*)d_out;

  static bool attr_done = false;
  if (!attr_done) {
    cudaFuncSetAttribute(k_yagg, cudaFuncAttributeMaxDynamicSharedMemorySize, SM_YAGG);
    cudaFuncSetAttribute(k_gates, cudaFuncAttributeMaxDynamicSharedMemorySize, SM_GATES);
    cudaFuncSetAttribute(k_alpha, cudaFuncAttributeMaxDynamicSharedMemorySize, SM_ALPHA);
    attr_done = true;
  }

  k_pack<<<2048, 256>>>(feat, W_in, W_og, W_ih, W_hh, W_u, W_v,
                        b_in, b_og, b_ih, b_hh);
  k_build_adj<<<NEDGE / 256, 256>>>(src, dst);

  k_yagg<<<dim3(NNODE / 128, 2), 256, SM_YAGG>>>();
  k_gates<<<dim3(4, NNODE / 64), 256, SM_GATES>>>();
  k_alpha<<<NNODE / 128, 256, SM_ALPHA>>>(cnt, w_e, b_v, out);
}

// round 17
// speedup vs baseline: 1.5621x; 1.1553x over previous
#include <cuda_runtime.h>
#include <cuda_fp16.h>
#include <cstdint>

#define NGRAPH 8192
#define NNODE (NGRAPH * 32)
#define NEDGE 524288

typedef __half h16;

// ================= static device scratch =================
__device__ __align__(16) h16  g_adjh[NGRAPH * 1024];   // fp16 counts
__device__ __align__(16) h16  g_featH[(size_t)NNODE * 128];
__device__ __align__(16) h16  g_AggH[(size_t)NNODE * 256];
__device__ __align__(16) h16  g_HNh[(size_t)NNODE * 128];
__device__ __align__(16) float g_HNlast[(size_t)NGRAPH * 128];
__device__ __align__(16) h16  g_Wio[256 * 128];
__device__ __align__(16) h16  g_Wg[512 * 384];
__device__ __align__(16) h16  g_Wu[128 * 128];
__device__ __align__(16) h16  g_Wv[128 * 128];
__device__ __align__(16) float g_biasY[256];
__device__ __align__(16) float g_biasG[512];

// ================= helpers =================
__device__ __forceinline__ uint32_t smem_to_u32(const void* p) {
  uint32_t a;
  asm("{ .reg .u64 tmp; cvta.to.shared.u64 tmp, %1; cvt.u32.u64 %0, tmp; }"
      : "=r"(a) : "l"(p));
  return a;
}
#define SWZ(off) ((off) ^ (((off) >> 3) & 0x70))

__device__ __forceinline__ void cp16(uint32_t dst, const void* src) {
  asm volatile("cp.async.cg.shared.global [%0], [%1], 16;" ::"r"(dst), "l"(src));
}
#define CP_COMMIT() asm volatile("cp.async.commit_group;" ::: "memory")
#define CP_WAIT(n) asm volatile("cp.async.wait_group %0;" ::"n"(n) : "memory")

__device__ __forceinline__ void ldsm_x4(uint32_t addr, uint32_t* r) {
  asm volatile("ldmatrix.sync.aligned.m8n8.x4.shared.b16 {%0,%1,%2,%3}, [%4];"
               : "=r"(r[0]), "=r"(r[1]), "=r"(r[2]), "=r"(r[3]) : "r"(addr));
}
__device__ __forceinline__ void ldsm_x4_t(uint32_t addr, uint32_t* r) {
  asm volatile("ldmatrix.sync.aligned.m8n8.x4.trans.shared.b16 {%0,%1,%2,%3}, [%4];"
               : "=r"(r[0]), "=r"(r[1]), "=r"(r[2]), "=r"(r[3]) : "r"(addr));
}
__device__ __forceinline__ void mma16816(float* d, const uint32_t* a,
                                         const uint32_t* b) {
  asm volatile(
      "mma.sync.aligned.m16n8k16.row.col.f32.f16.f16.f32 "
      "{%0,%1,%2,%3}, {%4,%5,%6,%7}, {%8,%9}, {%0,%1,%2,%3};"
      : "+f"(d[0]), "+f"(d[1]), "+f"(d[2]), "+f"(d[3])
      : "r"(a[0]), "r"(a[1]), "r"(a[2]), "r"(a[3]), "r"(b[0]), "r"(b[1]));
}

// HW tanh (sm_75+): 1 MUFU op
__device__ __forceinline__ float htanh(float x) {
  float y;
  asm("tanh.approx.f32 %0, %1;" : "=f"(y) : "f"(x));
  return y;
}
__device__ __forceinline__ float sigf(float x) {
  return fmaf(0.5f, htanh(0.5f * x), 0.5f);
}
__device__ __forceinline__ float tanh_fast(float x) { return htanh(x); }
__device__ __forceinline__ float h2f(h16 v) { return __half2float(v); }
__device__ __forceinline__ uint32_t pack2h(float a, float b) {
  __half2 h = __floats2half2_rn(a, b);
  return *(uint32_t*)&h;
}

// ================= adjacency build (zeroing merged into k_pack) ==========
__global__ void k_build_adj(const int* __restrict__ src, const int* __restrict__ dst) {
  int e = blockIdx.x * blockDim.x + threadIdx.x;
  if (e >= NEDGE) return;
  int d = dst[e];
  int s = src[e];
  int idx = ((d >> 5) << 10) + ((d & 31) << 5) + (s & 31);
  __half2 v = (idx & 1) ? __floats2half2_rn(0.f, 1.f)
                        : __floats2half2_rn(1.f, 0.f);
  atomicAdd(&((__half2*)g_adjh)[idx >> 1], v);
}

// ================= weight pack + feat convert + adj zero =================
__global__ void k_pack(const float* __restrict__ feat,
                       const float* __restrict__ W_in, const float* __restrict__ W_og,
                       const float* __restrict__ W_ih, const float* __restrict__ W_hh,
                       const float* __restrict__ W_u, const float* __restrict__ W_v,
                       const float* __restrict__ b_in, const float* __restrict__ b_og,
                       const float* __restrict__ b_ih, const float* __restrict__ b_hh) {
  int i0 = blockIdx.x * 256 + threadIdx.x;
  int stride = gridDim.x * 256;
  {
    int4* p = (int4*)g_adjh;
    const int n4 = NGRAPH * 1024 * 2 / 16;
    int4 z = make_int4(0, 0, 0, 0);
    for (int i = i0; i < n4; i += stride) p[i] = z;
  }
  {
    const float4* f4 = (const float4*)feat;
    const size_t n4 = (size_t)NNODE * 32;
    for (size_t i = i0; i < n4; i += stride) {
      float4 v = f4[i];
      __half2* dstp = (__half2*)&g_featH[i * 4];
      dstp[0] = __floats2half2_rn(v.x, v.y);
      dstp[1] = __floats2half2_rn(v.z, v.w);
    }
  }
  for (int i = i0; i < 256 * 128; i += stride) {
    int r = i >> 7, c = i & 127;
    float v = (r < 128) ? W_in[r * 128 + c] : W_og[(r - 128) * 128 + c];
    g_Wio[i] = __float2half_rn(v);
  }
  for (int i = i0; i < 512 * 384; i += stride) {
    int r = i / 384, c = i % 384;
    int blk = r >> 7, rr = r & 127;
    float v;
    if (blk == 0)      v = (c < 256) ? W_ih[rr * 256 + c] : W_hh[rr * 128 + (c - 256)];
    else if (blk == 1) v = (c < 256) ? W_ih[(128 + rr) * 256 + c] : W_hh[(128 + rr) * 128 + (c - 256)];
    else if (blk == 2) v = (c < 256) ? W_ih[(256 + rr) * 256 + c] : 0.f;
    else               v = (c < 256) ? 0.f : W_hh[(256 + rr) * 128 + (c - 256)];
    g_Wg[i] = __float2half_rn(v);
  }
  for (int i = i0; i < 128 * 128; i += stride) {
    g_Wu[i] = __float2half_rn(W_u[i]);
    g_Wv[i] = __float2half_rn(W_v[i]);
  }
  for (int i = i0; i < 256; i += stride)
    g_biasY[i] = (i < 128) ? b_in[i] : b_og[i - 128];
  for (int i = i0; i < 512; i += stride) {
    float v;
    if (i < 256)      v = b_ih[i] + b_hh[i];
    else if (i < 384) v = b_ih[i];
    else              v = b_hh[i - 128];
    g_biasG[i] = v;
  }
}

// ================= Y GEMM + tensorized aggregation (2 CTA/SM) ====
#define YSG 32768
#define Y_ADJ 65536
#define Y_RDEG (65536 + 10240)
#define SM_YAGG (65536 + 10240 + 512)

__global__ void __launch_bounds__(256, 2) k_yagg() {
  extern __shared__ __align__(1024) char smem[];
  const uint32_t sb = smem_to_u32(smem);
  const int tid = threadIdx.x;
  const int lid = tid & 31, wid = tid >> 5;
  const int m0 = blockIdx.x * 128;
  const int nb = blockIdx.y;
  const int g0 = m0 >> 5;
  const int wm0 = (wid & 3) * 32, wn0 = (wid >> 2) * 64;

  const h16* Bh = g_Wio + (size_t)nb * 128 * 128;
  float* rdeg = (float*)(smem + Y_RDEG);

  auto issue = [&](int kc, int s) {
    uint32_t base = sb + s * YSG;
#pragma unroll
    for (int i = 0; i < 4; i++) {
      int u = tid + 256 * i;
      int r = u >> 3, seg = u & 7;
      uint32_t d = SWZ(r * 128 + seg * 16);
      cp16(base + d, g_featH + (size_t)(m0 + r) * 128 + kc + seg * 8);
      cp16(base + 16384 + d, Bh + (size_t)r * 128 + kc + seg * 8);
    }
    CP_COMMIT();
  };

  issue(0, 0);
  issue(64, 1);

  const h16* adjg = g_adjh + ((size_t)g0 << 10);
#pragma unroll
  for (int i = 0; i < 16; i++) {
    int u = tid + 256 * i;
    int gl = u >> 10, rem = u & 1023;
    int n = rem >> 5, k = rem & 31;
    int row, col;
    if (nb == 0) { row = gl * 32 + n; col = k; }
    else { row = gl * 32 + k; col = n; }
    *(h16*)(smem + Y_ADJ + row * 80 + col * 2) = adjg[u];
  }
  __syncthreads();
  if (tid < 128) {
    const __half2* rowp = (const __half2*)(smem + Y_ADJ + tid * 80);
    float s = 0.f;
#pragma unroll
    for (int k = 0; k < 16; k++) {
      float2 v = __half22float2(rowp[k]);
      s += v.x + v.y;
    }
    rdeg[tid] = 1.f / fmaxf(s, 1.f);
  }

  float acc[2][8][4];
#pragma unroll
  for (int mi = 0; mi < 2; mi++)
#pragma unroll
    for (int ni = 0; ni < 8; ni++)
#pragma unroll
      for (int q = 0; q < 4; q++) acc[mi][ni][q] = 0.f;

  const int j = lid >> 3, rr = lid & 7;
#pragma unroll
  for (int c = 0; c < 2; c++) {
    if (c == 0) CP_WAIT(1); else CP_WAIT(0);
    __syncthreads();
    const uint32_t st = sb + c * YSG;
#pragma unroll
    for (int kk = 0; kk < 4; kk++) {
      uint32_t ah[2][4], bh[8][2];
#pragma unroll
      for (int mi = 0; mi < 2; mi++) {
        int row = wm0 + mi * 16 + (j & 1) * 8 + rr;
        int kb = kk * 32 + (j >> 1) * 16;
        ldsm_x4(st + SWZ(row * 128 + kb), ah[mi]);
      }
#pragma unroll
      for (int p = 0; p < 4; p++) {
        int n = wn0 + p * 16 + (j >> 1) * 8 + rr;
        int kb = kk * 32 + (j & 1) * 16;
        uint32_t t[4];
        ldsm_x4(st + 16384 + SWZ(n * 128 + kb), t);
        bh[2 * p][0] = t[0]; bh[2 * p][1] = t[1];
        bh[2 * p + 1][0] = t[2]; bh[2 * p + 1][1] = t[3];
      }
#pragma unroll
      for (int mi = 0; mi < 2; mi++)
#pragma unroll
        for (int ni = 0; ni < 8; ni++)
          mma16816(acc[mi][ni], ah[mi], bh[ni]);
    }
  }
  __syncthreads();

  const int gp = lid >> 2, tg = lid & 3;
#pragma unroll
  for (int mi = 0; mi < 2; mi++)
#pragma unroll
    for (int ni = 0; ni < 8; ni++) {
      int r = wm0 + mi * 16 + gp;
      int c = wn0 + ni * 8 + tg * 2;
      float b0 = g_biasY[nb * 128 + c], b1 = g_biasY[nb * 128 + c + 1];
      uint32_t tileo = (c >> 6) * 16384;
      *(uint32_t*)(smem + tileo + SWZ(r * 128 + (c & 63) * 2)) =
          pack2h(acc[mi][ni][0] + b0, acc[mi][ni][1] + b1);
      *(uint32_t*)(smem + tileo + SWZ((r + 8) * 128 + (c & 63) * 2)) =
          pack2h(acc[mi][ni][2] + b0, acc[mi][ni][3] + b1);
    }
  __syncthreads();

  {
    const int arow = wid * 16;
    const int krow0 = (wid >> 1) * 32;
    uint32_t af[2][4];
#pragma unroll
    for (int ks = 0; ks < 2; ks++) {
      uint32_t addr = sb + Y_ADJ + (arow + (j & 1) * 8 + rr) * 80 +
                      (j >> 1) * 16 + ks * 32;
      ldsm_x4(addr, af[ks]);
    }
    float accC[16][4];
#pragma unroll
    for (int nf = 0; nf < 16; nf++)
#pragma unroll
      for (int q = 0; q < 4; q++) accC[nf][q] = 0.f;
#pragma unroll
    for (int p = 0; p < 8; p++) {
#pragma unroll
      for (int ks = 0; ks < 2; ks++) {
        int krow = krow0 + ks * 16 + (j & 1) * 8 + rr;
        int c = p * 16 + (j >> 1) * 8;
        uint32_t t[4];
        ldsm_x4_t(sb + (c >> 6) * 16384 + SWZ(krow * 128 + (c & 63) * 2), t);
        mma16816(accC[2 * p], af[ks], t);
        mma16816(accC[2 * p + 1], af[ks], t + 2);
      }
    }
#pragma unroll
    for (int nf = 0; nf < 16; nf++) {
      int col = nf * 8 + tg * 2;
      int r0 = arow + gp, r1 = arow + gp + 8;
      float rd0 = rdeg[r0], rd1 = rdeg[r1];
      size_t o0 = (size_t)(m0 + r0) * 256 + nb * 128 + col;
      size_t o1 = (size_t)(m0 + r1) * 256 + nb * 128 + col;
      *(uint32_t*)&g_AggH[o0] = pack2h(accC[nf][0] * rd0, accC[nf][1] * rd0);
      *(uint32_t*)&g_AggH[o1] = pack2h(accC[nf][2] * rd1, accC[nf][3] * rd1);
    }
  }
}

// ===== gates: 32-col slice, 3 CTA/SM, unrolled pipeline, hoisted addrs ====
#define GA 0                        // 3 x 8KB A stages
#define GB 24576                    // 3 x 12KB B stages
#define G_BIAS (24576 + 36864)      // 61440
#define SM_GATES (61440 + 2048)     // 63488

__global__ void __launch_bounds__(256, 3) k_gates() {
  extern __shared__ __align__(1024) char smem[];
  const uint32_t sb = smem_to_u32(smem);
  float* sbias = (float*)(smem + G_BIAS);
  const int tid = threadIdx.x;
  const int lid = tid & 31, wid = tid >> 5;
  const int nh = blockIdx.x;            // 0..3
  const int m0 = blockIdx.y * 64;
  const int cs = nh * 32;               // global gate-col base
  const int gate = wid >> 1;
  const int wm0g = (wid & 1) * 32;

  // ---- hoisted per-thread issue addressing ----
  const int rA0 = tid >> 3, segA = tid & 7;
  const int rA1 = (tid + 256) >> 3;
  const uint32_t dA0 = SWZ(rA0 * 128 + segA * 16);
  const uint32_t dA1 = SWZ(rA1 * 128 + segA * 16);
  const h16* aggS0 = g_AggH + (size_t)(m0 + rA0) * 256 + segA * 8;
  const h16* aggS1 = g_AggH + (size_t)(m0 + rA1) * 256 + segA * 8;
  const h16* featS0 = g_featH + (size_t)(m0 + rA0) * 128 + segA * 8;
  const h16* featS1 = g_featH + (size_t)(m0 + rA1) * 128 + segA * 8;
  const h16* wgBase = g_Wg + (size_t)(cs + rA0) * 384 + segA * 8;
  const uint32_t dB = dA0;

  auto issue = [&](int ch) {   // ch is compile-time under full unroll
    uint32_t baseA = sb + GA + (ch % 3) * 8192;
    if (ch < 4) {
      cp16(baseA + dA0, aggS0 + ch * 64);
      cp16(baseA + dA1, aggS1 + ch * 64);
    } else {
      cp16(baseA + dA0, featS0 + (ch - 4) * 64);
      cp16(baseA + dA1, featS1 + (ch - 4) * 64);
    }
    uint32_t baseB = sb + GB + (ch % 3) * 12288;
    cp16(baseB + dB, wgBase + ch * 64);
    cp16(baseB + 4096 + dB, wgBase + 128 * 384 + ch * 64);
    cp16(baseB + 8192 + dB,
         wgBase + (ch >= 4 ? 3 : 2) * 128 * 384 + ch * 64);
    CP_COMMIT();
  };
  issue(0);
  issue(1);
  for (int i = tid; i < 512; i += 256) sbias[i] = g_biasG[i];

  float acc[2][4][4];
#pragma unroll
  for (int mi = 0; mi < 2; mi++)
#pragma unroll
    for (int ni = 0; ni < 4; ni++)
#pragma unroll
      for (int q = 0; q < 4; q++) acc[mi][ni][q] = 0.f;

  // ---- hoisted ldsm offsets (within a stage) ----
  const int j = lid >> 3, rr = lid & 7;
  const uint32_t aO = SWZ((wm0g + (j & 1) * 8 + rr) * 128 + (j >> 1) * 16);
  const uint32_t aO1 = SWZ((wm0g + 16 + (j & 1) * 8 + rr) * 128 + (j >> 1) * 16);
  const uint32_t bO = SWZ(((j >> 1) * 8 + rr) * 128 + (j & 1) * 16);
  const uint32_t bO1 = SWZ((16 + (j >> 1) * 8 + rr) * 128 + (j & 1) * 16);
  const uint32_t bslotoff = ((gate < 2) ? gate : 2) * 4096;

#pragma unroll
  for (int ch = 0; ch < 6; ch++) {
    if (ch < 5) CP_WAIT(1); else CP_WAIT(0);
    __syncthreads();
    if (ch + 2 < 6) issue(ch + 2);
    bool active = (gate == 2) ? (ch < 4) : (gate == 3) ? (ch >= 4) : true;
    if (active) {
      const uint32_t abase = sb + GA + (ch % 3) * 8192;
      const uint32_t bbase = sb + GB + (ch % 3) * 12288 + bslotoff;
#pragma unroll
      for (int kk = 0; kk < 4; kk++) {
        const uint32_t ko = kk * 32;   // bits[5:6] only; XOR-safe vs hoisted bases
        uint32_t ah[2][4], bh[4][2];
        ldsm_x4(abase + (aO ^ SWZ(ko)), ah[0]);
        ldsm_x4(abase + (aO1 ^ SWZ(ko)), ah[1]);
        {
          uint32_t t[4];
          ldsm_x4(bbase + (bO ^ SWZ(ko)), t);
          bh[0][0] = t[0]; bh[0][1] = t[1];
          bh[1][0] = t[2]; bh[1][1] = t[3];
          ldsm_x4(bbase + (bO1 ^ SWZ(ko)), t);
          bh[2][0] = t[0]; bh[2][1] = t[1];
          bh[3][0] = t[2]; bh[3][1] = t[3];
        }
#pragma unroll
        for (int mi = 0; mi < 2; mi++)
#pragma unroll
          for (int ni = 0; ni < 4; ni++)
            mma16816(acc[mi][ni], ah[mi], bh[ni]);
      }
    }
  }
  __syncthreads();

  // ---- fp16 exchange in dead B region: 4 slabs x 64 rows x stride 34 ----
  h16* sG = (h16*)(smem + GB);
  const int gp = lid >> 2, tg = lid & 3;
#pragma unroll
  for (int mi = 0; mi < 2; mi++)
#pragma unroll
    for (int ni = 0; ni < 4; ni++) {
      int r = wm0g + mi * 16 + gp;
      int c = ni * 8 + tg * 2;
      int colg = cs + c;
      float v[4] = {acc[mi][ni][0], acc[mi][ni][1],
                    acc[mi][ni][2], acc[mi][ni][3]};
      if (gate == 0) {
        v[0] = sigf(v[0] + sbias[colg]); v[1] = sigf(v[1] + sbias[colg + 1]);
        v[2] = sigf(v[2] + sbias[colg]); v[3] = sigf(v[3] + sbias[colg + 1]);
      } else if (gate == 1) {
        v[0] = sigf(v[0] + sbias[128 + colg]); v[1] = sigf(v[1] + sbias[129 + colg]);
        v[2] = sigf(v[2] + sbias[128 + colg]); v[3] = sigf(v[3] + sbias[129 + colg]);
      } else if (gate == 2) {
        v[0] += sbias[256 + colg]; v[1] += sbias[257 + colg];
        v[2] += sbias[256 + colg]; v[3] += sbias[257 + colg];
      } else {
        v[0] += sbias[384 + colg]; v[1] += sbias[385 + colg];
        v[2] += sbias[384 + colg]; v[3] += sbias[385 + colg];
      }
      *(uint32_t*)&sG[(gate * 64 + r) * 34 + c] = pack2h(v[0], v[1]);
      *(uint32_t*)&sG[(gate * 64 + r + 8) * 34 + c] = pack2h(v[2], v[3]);
    }
  __syncthreads();

  // ---- GRU elementwise: 64 rows x 32 cols -> 8 cols per thread ----
  {
    const int row = tid >> 2, q = tid & 3;
    const int grow = m0 + row;
    const bool lastrow = (grow & 31) == 31;
    const int fstage = (4 + (nh >> 1)) % 3;
    const int fcb = (nh & 1) * 32;
    __align__(16) h16 oh[8];
#pragma unroll
    for (int c2 = 0; c2 < 4; c2++) {
      int lc = q * 8 + c2 * 2;
      uint32_t fh = *(uint32_t*)(smem + GA + fstage * 8192 +
                                 SWZ(row * 128 + (fcb + lc) * 2));
      float2 fvp = __half22float2(*(__half2*)&fh);
#pragma unroll
      for (int c1 = 0; c1 < 2; c1++) {
        int lcc = lc + c1;
        float r_ = h2f(sG[row * 34 + lcc]);
        float z_ = h2f(sG[(64 + row) * 34 + lcc]);
        float is = h2f(sG[(128 + row) * 34 + lcc]);
        float hs = h2f(sG[(192 + row) * 34 + lcc]);
        float ng = tanh_fast(is + r_ * hs);
        float f = (c1 == 0) ? fvp.x : fvp.y;
        float hn = (1.f - z_) * ng + z_ * f;
        oh[c2 * 2 + c1] = __float2half_rn(hn);
        if (lastrow) g_HNlast[(size_t)(grow >> 5) * 128 + cs + lcc] = hn;
      }
    }
    *(int4*)&g_HNh[(size_t)grow * 128 + cs + q * 8] = *(int4*)oh;
  }
}

// ========= U GEMM + FV + attention + readout (2 CTA/SM, fv fused) =========
#define SG 32768
#define A_MISC (2 * SG)
#define A_WV (2 * SG + 6656)
#define SM_ALPHA (A_WV + 32768)

__global__ void __launch_bounds__(256, 2) k_alpha(const float* __restrict__ cnt,
                                                  const float* __restrict__ we,
                                                  const float* __restrict__ b_v,
                                                  float* __restrict__ out) {
  extern __shared__ __align__(1024) char smem[];
  const uint32_t sb = smem_to_u32(smem);
  const int tid = threadIdx.x;
  const int lid = tid & 31, wid = tid >> 5;
  const int m0 = blockIdx.x * 128;
  const int g0 = m0 >> 5;
  const int wm0 = (wid & 3) * 32, wn0 = (wid >> 2) * 64;

  float* sFV = (float*)(smem + A_MISC);
  float* swe = sFV + 512;
  float* scnt = swe + 128;
  float* sPart = scnt + 128;
  float* sAl = sPart + 256;
  float* sLast = sAl + 128;

  auto issue = [&](int kc, int s) {
    uint32_t base = sb + s * SG;
#pragma unroll
    for (int i = 0; i < 4; i++) {
      int u = tid + 256 * i;
      int r = u >> 3, seg = u & 7;
      uint32_t d = SWZ(r * 128 + seg * 16);
      cp16(base + d, g_HNh + (size_t)(m0 + r) * 128 + kc + seg * 8);
      cp16(base + 16384 + d, g_Wu + (size_t)r * 128 + kc + seg * 8);
    }
  };

  issue(0, 0);
#pragma unroll
  for (int i = 0; i < 8; i++) {
    int u = tid + 256 * i;
    cp16(sb + A_WV + u * 16, g_Wv + u * 8);
  }
  CP_COMMIT();
  issue(64, 1);
  CP_COMMIT();

  if (tid < 128) { swe[tid] = we[tid]; scnt[tid] = cnt[m0 + tid]; }
#pragma unroll
  for (int i = 0; i < 2; i++) {
    int e = tid + 256 * i;
    sLast[e] = g_HNlast[(size_t)g0 * 128 + e];
  }

  float acc[2][8][4];
#pragma unroll
  for (int mi = 0; mi < 2; mi++)
#pragma unroll
    for (int ni = 0; ni < 8; ni++)
#pragma unroll
      for (int q = 0; q < 4; q++) acc[mi][ni][q] = 0.f;

  const int j = lid >> 3, rr = lid & 7;
#pragma unroll
  for (int c = 0; c < 2; c++) {
    if (c == 0) CP_WAIT(1); else CP_WAIT(0);
    __syncthreads();
    const uint32_t st = sb + c * SG;
#pragma unroll
    for (int kk = 0; kk < 4; kk++) {
      uint32_t ah[2][4], bh[8][2];
#pragma unroll
      for (int mi = 0; mi < 2; mi++) {
        int row = wm0 + mi * 16 + (j & 1) * 8 + rr;
        int kb = kk * 32 + (j >> 1) * 16;
        ldsm_x4(st + SWZ(row * 128 + kb), ah[mi]);
      }
#pragma unroll
      for (int p = 0; p < 4; p++) {
        int n = wn0 + p * 16 + (j >> 1) * 8 + rr;
        int kb = kk * 32 + (j & 1) * 16;
        uint32_t t[4];
        ldsm_x4(st + 16384 + SWZ(n * 128 + kb), t);
        bh[2 * p][0] = t[0]; bh[2 * p][1] = t[1];
        bh[2 * p + 1][0] = t[2]; bh[2 * p + 1][1] = t[3];
      }
#pragma unroll
      for (int mi = 0; mi < 2; mi++)
#pragma unroll
        for (int ni = 0; ni < 8; ni++)
          mma16816(acc[mi][ni], ah[mi], bh[ni]);
    }
  }
  __syncthreads();

  // FV = HNlast(f32) . Wv^T + b_v
#pragma unroll
  for (int e2 = 0; e2 < 2; e2++) {
    int e = tid + 256 * e2;
    int gl = e >> 7, jx = e & 127;
    const __half2* wv = (const __half2*)(smem + A_WV + jx * 256);
    const float* hl = sLast + gl * 128;
    float s = b_v[jx];
#pragma unroll 8
    for (int kk = 0; kk < 64; kk++) {
      int k2 = (kk + jx) & 63;
      float2 w = __half22float2(wv[k2]);
      s += hl[2 * k2] * w.x + hl[2 * k2 + 1] * w.y;
    }
    sFV[e] = s;
  }
  __syncthreads();

  const int gp = lid >> 2, tg = lid & 3;
#pragma unroll
  for (int mi = 0; mi < 2; mi++) {
    int base = wm0 + mi * 16;
    int gl = base >> 5;
    float p0 = 0.f, p1 = 0.f;
#pragma unroll
    for (int ni = 0; ni < 8; ni++) {
      int jx = wn0 + ni * 8 + tg * 2;
      float fv0 = sFV[gl * 128 + jx], fv1 = sFV[gl * 128 + jx + 1];
      float w0 = swe[jx], w1 = swe[jx + 1];
      p0 += w0 * sigf(acc[mi][ni][0] + fv0) + w1 * sigf(acc[mi][ni][1] + fv1);
      p1 += w0 * sigf(acc[mi][ni][2] + fv0) + w1 * sigf(acc[mi][ni][3] + fv1);
    }
    p0 += __shfl_xor_sync(0xffffffffu, p0, 1);
    p0 += __shfl_xor_sync(0xffffffffu, p0, 2);
    p1 += __shfl_xor_sync(0xffffffffu, p1, 1);
    p1 += __shfl_xor_sync(0xffffffffu, p1, 2);
    if (tg == 0) {
      sPart[(wid >> 2) * 128 + base + gp] = p0;
      sPart[(wid >> 2) * 128 + base + gp + 8] = p1;
    }
  }
  __syncthreads();
  if (tid < 128) sAl[tid] = (sPart[tid] + sPart[128 + tid]) * scnt[tid];
  __syncthreads();

  {
    int gl = tid >> 6, jp = tid & 63;
    int col0 = 2 * jp;
    int stg = col0 >> 6, cl = col0 & 63;
    float a0 = 0.f, a1 = 0.f;
#pragma unroll
    for (int n = 0; n < 32; n++) {
      uint32_t hv = *(uint32_t*)(smem + stg * SG +
                                 SWZ((gl * 32 + n) * 128 + cl * 2));
      float2 h = __half22float2(*(__half2*)&hv);
      float al = sAl[gl * 32 + n];
      a0 += h.x * al;
      a1 += h.y * al;
    }
    size_t ob = (size_t)(g0 + gl) * 256;
    *(float2*)&out[ob + col0] = make_float2(a0, a1);
    *(float2*)&out[ob + 128 + col0] =
        make_float2(sLast[gl * 128 + col0], sLast[gl * 128 + col0 + 1]);
  }
}

// ================= host =================
extern "C" void kernel_launch(void* const* d_in, const int* in_sizes, int n_in,
                              void* d_out, int out_size) {
  const float* feat = (const float*)d_in[0];
  const float* cnt  = (const float*)d_in[1];
  const float* W_in = (const float*)d_in[2];
  const float* b_in = (const float*)d_in[3];
  const float* W_og = (const float*)d_in[4];
  const float* b_og = (const float*)d_in[5];
  const float* W_ih = (const float*)d_in[6];
  const float* b_ih = (const float*)d_in[7];
  const float* W_hh = (const float*)d_in[8];
  const float* b_hh = (const float*)d_in[9];
  const float* W_u  = (const float*)d_in[10];
  const float* W_v  = (const float*)d_in[11];
  const float* b_v  = (const float*)d_in[12];
  const float* w_e  = (const float*)d_in[13];
  const int*   src  = (const int*)d_in[14];
  const int*   dst  = (const int*)d_in[15];
  float* out = (float*)d_out;

  static bool attr_done = false;
  if (!attr_done) {
    cudaFuncSetAttribute(k_yagg, cudaFuncAttributeMaxDynamicSharedMemorySize, SM_YAGG);
    cudaFuncSetAttribute(k_gates, cudaFuncAttributeMaxDynamicSharedMemorySize, SM_GATES);
    cudaFuncSetAttribute(k_alpha, cudaFuncAttributeMaxDynamicSharedMemorySize, SM_ALPHA);
    attr_done = true;
  }

  k_pack<<<2048, 256>>>(feat, W_in, W_og, W_ih, W_hh, W_u, W_v,
                        b_in, b_og, b_ih, b_hh);
  k_build_adj<<<NEDGE / 256, 256>>>(src, dst);

  k_yagg<<<dim3(NNODE / 128, 2), 256, SM_YAGG>>>();
  k_gates<<<dim3(4, NNODE / 64), 256, SM_GATES>>>();
  k_alpha<<<NNODE / 128, 256, SM_ALPHA>>>(cnt, w_e, b_v, out);
}